// round 2
// baseline (speedup 1.0000x reference)
#include <cuda_runtime.h>
#include <math.h>

// ---------------- problem constants ----------------
#define NN   50000
#define EE   800000
#define EP   (EE + NN)        // edges + self loops
#define KIN  128
#define C1   256              // 8 heads * 32
#define NH   8
#define HD   32
#define NC   10
#define NEG  0.2f

// ---------------- scratch (device globals; no allocs allowed) ----------------
// NOTE: __align__(256) is load-bearing — these are accessed as float4.
__device__ __align__(256) float g_h1[(size_t)NN * C1];      // x @ W1
__device__ __align__(256) float g_h1out[(size_t)NN * C1];   // layer-1 out (bias+ELU)
__device__ __align__(256) float g_as1[NN * NH];
__device__ __align__(256) float g_ad1[NN * NH];
__device__ __align__(256) float g_h2[NN * 12];              // 10 logits + a_s2 + a_d2
__device__ __align__(256) float g_w2aug[C1 * 12];
__device__ __align__(256) int   g_rowptr[NN + 1];
__device__ __align__(256) int   g_cursor[NN];
__device__ __align__(256) int   g_counts[NN];
__device__ __align__(256) int   g_esrc[EP];
__device__ __align__(256) int   g_bsums[256];
__device__ int   g_is64;

// ---------------- helpers ----------------
__device__ __forceinline__ int eidx(const void* p, long long i, int is64) {
    return is64 ? (int)((const long long*)p)[i] : ((const int*)p)[i];
}
__device__ __forceinline__ float lrelu(float x) { return x > 0.f ? x : NEG * x; }
__device__ __forceinline__ float elu1(float x)  { return x > 0.f ? x : (__expf(x) - 1.f); }

// ---------------- dtype sniffing (int64 vs int32 edge_index) ----------------
// int32 pairs misread as int64 are >= 2^32 (or have garbage high words), so
// "64 consecutive in-range int64 values" identifies real int64 data.
__global__ void k_detect(const void* ei) {
    const long long* p = (const long long*)ei;
    int ok = 1;
    for (int i = 0; i < 64; i++) {
        long long v = p[i];
        if (v < 0 || v >= NN) ok = 0;
    }
    g_is64 = ok;
}

// ---------------- CSR build ----------------
__global__ void k_zero() {
    int i = blockIdx.x * blockDim.x + threadIdx.x;
    if (i < NN) g_counts[i] = 0;
}

__global__ void k_hist(const void* ei) {
    int i = blockIdx.x * blockDim.x + threadIdx.x;
    if (i >= EP) return;
    int is64 = g_is64;
    int d = (i < EE) ? eidx(ei, (long long)EE + i, is64) : (i - EE);
    atomicAdd(&g_counts[d], 1);
}

__global__ void k_scan1() {   // per-block sums (196 blocks x 256)
    __shared__ int s[256];
    int t = threadIdx.x;
    int i = blockIdx.x * 256 + t;
    s[t] = (i < NN) ? g_counts[i] : 0;
    __syncthreads();
    for (int o = 128; o > 0; o >>= 1) {
        if (t < o) s[t] += s[t + o];
        __syncthreads();
    }
    if (t == 0) g_bsums[blockIdx.x] = s[0];
}

__global__ void k_scan2() {   // single block: exclusive scan of 196 block sums
    __shared__ int s[256];
    int t = threadIdx.x;
    int v = (t < 196) ? g_bsums[t] : 0;
    s[t] = v;
    __syncthreads();
    for (int o = 1; o < 256; o <<= 1) {
        int x = (t >= o) ? s[t - o] : 0;
        __syncthreads();
        s[t] += x;
        __syncthreads();
    }
    g_bsums[t] = s[t] - v;    // exclusive
}

__global__ void k_scan3() {   // rowptr = block offset + intra-block exclusive
    __shared__ int s[256];
    int t = threadIdx.x;
    int i = blockIdx.x * 256 + t;
    int v = (i < NN) ? g_counts[i] : 0;
    s[t] = v;
    __syncthreads();
    for (int o = 1; o < 256; o <<= 1) {
        int x = (t >= o) ? s[t - o] : 0;
        __syncthreads();
        s[t] += x;
        __syncthreads();
    }
    int excl = s[t] - v + g_bsums[blockIdx.x];
    if (i < NN) { g_rowptr[i] = excl; g_cursor[i] = excl; }
    if (i == 0) g_rowptr[NN] = EP;
}

__global__ void k_scatter(const void* ei) {
    int i = blockIdx.x * blockDim.x + threadIdx.x;
    if (i >= EP) return;
    int is64 = g_is64;
    int s, d;
    if (i < EE) {
        s = eidx(ei, i, is64);
        d = eidx(ei, (long long)EE + i, is64);
    } else {
        s = d = i - EE;
    }
    int pos = atomicAdd(&g_cursor[d], 1);
    g_esrc[pos] = s;
}

// ---------------- GEMM1: h1 = x @ W1  [50000,128]x[128,256] fp32 ----------------
__global__ void k_gemm1(const float* __restrict__ A, const float* __restrict__ B) {
    __shared__ float As[16][64];
    __shared__ float Bs[16][64];
    int tid = threadIdx.x;
    int bx = blockIdx.x, by = blockIdx.y;
    int row0 = by * 64;
    int ar = tid >> 2, ac = (tid & 3) << 2;     // A loader: 64 rows x 16 cols
    int br = tid >> 4, bc = (tid & 15) << 2;    // B loader: 16 rows x 64 cols
    int tx = tid & 15, ty = tid >> 4;           // 4x4 per thread
    float acc[4][4] = {};
    for (int k0 = 0; k0 < KIN; k0 += 16) {
        float4 av = make_float4(0.f, 0.f, 0.f, 0.f);
        int gr = row0 + ar;
        if (gr < NN) av = *(const float4*)(A + (size_t)gr * KIN + k0 + ac);
        As[ac + 0][ar] = av.x; As[ac + 1][ar] = av.y;
        As[ac + 2][ar] = av.z; As[ac + 3][ar] = av.w;
        *(float4*)&Bs[br][bc] =
            *(const float4*)(B + (size_t)(k0 + br) * C1 + bx * 64 + bc);
        __syncthreads();
#pragma unroll
        for (int k = 0; k < 16; k++) {
            float4 a = *(const float4*)&As[k][ty << 2];
            float4 b = *(const float4*)&Bs[k][tx << 2];
            acc[0][0] += a.x * b.x; acc[0][1] += a.x * b.y; acc[0][2] += a.x * b.z; acc[0][3] += a.x * b.w;
            acc[1][0] += a.y * b.x; acc[1][1] += a.y * b.y; acc[1][2] += a.y * b.z; acc[1][3] += a.y * b.w;
            acc[2][0] += a.z * b.x; acc[2][1] += a.z * b.y; acc[2][2] += a.z * b.z; acc[2][3] += a.z * b.w;
            acc[3][0] += a.w * b.x; acc[3][1] += a.w * b.y; acc[3][2] += a.w * b.z; acc[3][3] += a.w * b.w;
        }
        __syncthreads();
    }
    int gc = bx * 64 + (tx << 2);
#pragma unroll
    for (int i = 0; i < 4; i++) {
        int gr = row0 + (ty << 2) + i;
        if (gr < NN)
            *(float4*)(g_h1 + (size_t)gr * C1 + gc) =
                make_float4(acc[i][0], acc[i][1], acc[i][2], acc[i][3]);
    }
}

// ---------------- attention logits per (node, head) ----------------
__global__ void k_asd1(const float* __restrict__ asrc, const float* __restrict__ adst) {
    int tid = blockIdx.x * blockDim.x + threadIdx.x;
    if (tid >= NN * NH) return;
    int n = tid >> 3, h = tid & 7;
    const float4* hp = (const float4*)(g_h1 + (size_t)n * C1 + h * HD);
    const float4* sp = (const float4*)(asrc + h * HD);
    const float4* dp = (const float4*)(adst + h * HD);
    float s = 0.f, d = 0.f;
#pragma unroll
    for (int q = 0; q < 8; q++) {
        float4 a = hp[q], b = sp[q], c = dp[q];
        s += a.x * b.x + a.y * b.y + a.z * b.z + a.w * b.w;
        d += a.x * c.x + a.y * c.y + a.z * c.z + a.w * c.w;
    }
    g_as1[tid] = s;
    g_ad1[tid] = d;
}

// ---------------- layer-1 aggregation: warp per dst node, no atomics ----------
// Lane t owns channels [t*4, t*4+4) (head t/8) and [128+t*4, 128+t*4+4) (head 4+t/8).
__global__ void k_agg1(const float* __restrict__ b1) {
    int warp = (blockIdx.x * blockDim.x + threadIdx.x) >> 5;
    if (warp >= NN) return;
    int lane = threadIdx.x & 31;
    int n = warp;
    int hA = lane >> 3, hB = 4 + (lane >> 3);
    int beg = g_rowptr[n], end = g_rowptr[n + 1];
    float adA = g_ad1[n * NH + hA], adB = g_ad1[n * NH + hB];

    float mA = -1e30f, mB = -1e30f;
    for (int i = beg; i < end; i++) {
        int s = g_esrc[i];
        float eA = lrelu(g_as1[s * NH + hA] + adA);
        float eB = lrelu(g_as1[s * NH + hB] + adB);
        mA = fmaxf(mA, eA);
        mB = fmaxf(mB, eB);
    }

    float4 acc0 = make_float4(0.f, 0.f, 0.f, 0.f);
    float4 acc1 = make_float4(0.f, 0.f, 0.f, 0.f);
    float dA = 0.f, dB = 0.f;
    int i = beg;
    // unroll-by-2: two independent edge gathers in flight
    for (; i + 1 < end; i += 2) {
        int s0 = g_esrc[i], s1 = g_esrc[i + 1];
        const float4* hp0 = (const float4*)(g_h1 + (size_t)s0 * C1);
        const float4* hp1 = (const float4*)(g_h1 + (size_t)s1 * C1);
        float eA0 = lrelu(g_as1[s0 * NH + hA] + adA);
        float eB0 = lrelu(g_as1[s0 * NH + hB] + adB);
        float eA1 = lrelu(g_as1[s1 * NH + hA] + adA);
        float eB1 = lrelu(g_as1[s1 * NH + hB] + adB);
        float4 u0 = hp0[lane],      u1 = hp0[32 + lane];
        float4 v0 = hp1[lane],      v1 = hp1[32 + lane];
        float wA0 = __expf(eA0 - mA), wB0 = __expf(eB0 - mB);
        float wA1 = __expf(eA1 - mA), wB1 = __expf(eB1 - mB);
        dA += wA0 + wA1; dB += wB0 + wB1;
        acc0.x += wA0 * u0.x + wA1 * v0.x; acc0.y += wA0 * u0.y + wA1 * v0.y;
        acc0.z += wA0 * u0.z + wA1 * v0.z; acc0.w += wA0 * u0.w + wA1 * v0.w;
        acc1.x += wB0 * u1.x + wB1 * v1.x; acc1.y += wB0 * u1.y + wB1 * v1.y;
        acc1.z += wB0 * u1.z + wB1 * v1.z; acc1.w += wB0 * u1.w + wB1 * v1.w;
    }
    for (; i < end; i++) {
        int s = g_esrc[i];
        float eA = lrelu(g_as1[s * NH + hA] + adA);
        float eB = lrelu(g_as1[s * NH + hB] + adB);
        float wA = __expf(eA - mA);
        float wB = __expf(eB - mB);
        dA += wA; dB += wB;
        const float4* hp = (const float4*)(g_h1 + (size_t)s * C1);
        float4 v0 = hp[lane];
        float4 v1 = hp[32 + lane];
        acc0.x += wA * v0.x; acc0.y += wA * v0.y; acc0.z += wA * v0.z; acc0.w += wA * v0.w;
        acc1.x += wB * v1.x; acc1.y += wB * v1.y; acc1.z += wB * v1.z; acc1.w += wB * v1.w;
    }
    float iA = 1.f / dA, iB = 1.f / dB;
    const float4* bp = (const float4*)b1;
    float4 bb0 = bp[lane], bb1 = bp[32 + lane];
    float4 o0, o1;
    o0.x = elu1(acc0.x * iA + bb0.x); o0.y = elu1(acc0.y * iA + bb0.y);
    o0.z = elu1(acc0.z * iA + bb0.z); o0.w = elu1(acc0.w * iA + bb0.w);
    o1.x = elu1(acc1.x * iB + bb1.x); o1.y = elu1(acc1.y * iB + bb1.y);
    o1.z = elu1(acc1.z * iB + bb1.z); o1.w = elu1(acc1.w * iB + bb1.w);
    float4* op = (float4*)(g_h1out + (size_t)n * C1);
    op[lane] = o0;
    op[32 + lane] = o1;
}

// ---------------- fold att2 into W2: [256,12] = [W2 | W2@as2 | W2@ad2] --------
__global__ void k_w2aug(const float* __restrict__ W2,
                        const float* __restrict__ as2,
                        const float* __restrict__ ad2) {
    int k = blockIdx.x * blockDim.x + threadIdx.x;
    if (k >= C1) return;
    float s = 0.f, d = 0.f;
#pragma unroll
    for (int c = 0; c < NC; c++) {
        float w = W2[k * NC + c];
        g_w2aug[k * 12 + c] = w;
        s += w * as2[c];
        d += w * ad2[c];
    }
    g_w2aug[k * 12 + 10] = s;
    g_w2aug[k * 12 + 11] = d;
}

// ---------------- GEMM2: h2 = h1out @ W2aug  [50000,256]x[256,12] -------------
__global__ void k_gemm2() {
    __shared__ float Ws[C1 * 12];
    for (int i = threadIdx.x; i < C1 * 12; i += blockDim.x) Ws[i] = g_w2aug[i];
    __syncthreads();
    int n = blockIdx.x * blockDim.x + threadIdx.x;
    if (n >= NN) return;
    float acc[12];
#pragma unroll
    for (int c = 0; c < 12; c++) acc[c] = 0.f;
    const float4* xp = (const float4*)(g_h1out + (size_t)n * C1);
    for (int q = 0; q < 64; q++) {
        float4 x = xp[q];
        const float* w = &Ws[(q * 4) * 12];
#pragma unroll
        for (int c = 0; c < 12; c++)
            acc[c] += x.x * w[c] + x.y * w[12 + c] + x.z * w[24 + c] + x.w * w[36 + c];
    }
#pragma unroll
    for (int c = 0; c < 12; c++) g_h2[n * 12 + c] = acc[c];
}

// ---------------- layer-2 aggregation + log-softmax: warp per node ------------
__global__ void k_agg2(const float* __restrict__ b2, float* __restrict__ out) {
    int warp = (blockIdx.x * blockDim.x + threadIdx.x) >> 5;
    if (warp >= NN) return;
    int lane = threadIdx.x & 31;
    int n = warp;
    float ad2 = g_h2[n * 12 + 11];
    int beg = g_rowptr[n], end = g_rowptr[n + 1];

    float m = -1e30f;
    for (int i = beg + lane; i < end; i += 32) {
        int s = g_esrc[i];
        m = fmaxf(m, lrelu(g_h2[s * 12 + 10] + ad2));
    }
#pragma unroll
    for (int o = 16; o > 0; o >>= 1)
        m = fmaxf(m, __shfl_xor_sync(0xffffffffu, m, o));

    float acc = 0.f, den = 0.f;
    for (int i = beg; i < end; i++) {
        int s = g_esrc[i];
        float w = __expf(lrelu(g_h2[s * 12 + 10] + ad2) - m);
        den += w;
        if (lane < NC) acc += w * g_h2[s * 12 + lane];
    }
    float v = (lane < NC) ? (acc / den + b2[lane]) : -1e30f;
    float mx = v;
#pragma unroll
    for (int o = 16; o > 0; o >>= 1)
        mx = fmaxf(mx, __shfl_xor_sync(0xffffffffu, mx, o));
    float ex = (lane < NC) ? __expf(v - mx) : 0.f;
    float sm = ex;
#pragma unroll
    for (int o = 16; o > 0; o >>= 1)
        sm += __shfl_xor_sync(0xffffffffu, sm, o);
    if (lane < NC) out[(size_t)n * NC + lane] = v - mx - logf(sm);
}

// ---------------- launch ----------------
extern "C" void kernel_launch(void* const* d_in, const int* in_sizes, int n_in,
                              void* d_out, int out_size) {
    const float* x   = (const float*)d_in[0];
    const void*  ei  = d_in[1];
    const float* W1  = (const float*)d_in[2];
    const float* as1 = (const float*)d_in[3];
    const float* ad1 = (const float*)d_in[4];
    const float* b1  = (const float*)d_in[5];
    const float* W2  = (const float*)d_in[6];
    const float* as2 = (const float*)d_in[7];
    const float* ad2 = (const float*)d_in[8];
    const float* b2  = (const float*)d_in[9];
    float* out = (float*)d_out;

    k_detect<<<1, 1>>>(ei);
    k_zero<<<(NN + 255) / 256, 256>>>();
    k_hist<<<(EP + 255) / 256, 256>>>(ei);
    k_scan1<<<196, 256>>>();
    k_scan2<<<1, 256>>>();
    k_scan3<<<196, 256>>>();
    k_scatter<<<(EP + 255) / 256, 256>>>(ei);

    dim3 g1(4, (NN + 63) / 64);
    k_gemm1<<<g1, 256>>>(x, W1);
    k_asd1<<<(NN * NH + 255) / 256, 256>>>(as1, ad1);
    k_agg1<<<(NN + 7) / 8, 256>>>(b1);

    k_w2aug<<<1, 256>>>(W2, as2, ad2);
    k_gemm2<<<(NN + 127) / 128, 128>>>();
    k_agg2<<<(NN + 7) / 8, 256>>>(b2, out);
}

// round 3
// speedup vs baseline: 1.1487x; 1.1487x over previous
#include <cuda_runtime.h>
#include <math.h>

// ---------------- problem constants ----------------
#define NN   50000
#define EE   800000
#define EP   (EE + NN)        // edges + self loops
#define KIN  128
#define C1   256              // 8 heads * 32
#define NH   8
#define HD   32
#define NC   10
#define NEG  0.2f

// ---------------- scratch (device globals; no allocs allowed) ----------------
__device__ __align__(256) float g_h1[(size_t)NN * C1];      // x @ W1
__device__ __align__(256) float g_h1out[(size_t)NN * C1];   // layer-1 out (bias+ELU)
__device__ __align__(256) float g_as1[NN * NH];
__device__ __align__(256) float g_ad1[NN * NH];
__device__ __align__(256) float g_h2[NN * 12];              // 10 logits + a_s2 + a_d2
__device__ __align__(256) float g_w2aug[C1 * 12];
__device__ __align__(256) int   g_rowptr[NN + 1];
__device__ __align__(256) int   g_cursor[NN];
__device__ __align__(256) int   g_counts[NN];
__device__ __align__(256) int   g_esrc[EP];
__device__ __align__(256) int   g_bsums[256];
__device__ int   g_is64;

// ---------------- helpers ----------------
__device__ __forceinline__ int eidx(const void* p, long long i, int is64) {
    return is64 ? (int)((const long long*)p)[i] : ((const int*)p)[i];
}
__device__ __forceinline__ float lrelu(float x) { return x > 0.f ? x : NEG * x; }
__device__ __forceinline__ float elu1(float x)  { return x > 0.f ? x : (__expf(x) - 1.f); }

// ---------------- init: zero counts + dtype sniff (int64 vs int32) -----------
__global__ void k_init(const void* ei) {
    int i = blockIdx.x * blockDim.x + threadIdx.x;
    if (i < NN) g_counts[i] = 0;
    if (i == 0) {
        const long long* p = (const long long*)ei;
        int ok = 1;
        for (int q = 0; q < 64; q++) {
            long long v = p[q];
            if (v < 0 || v >= NN) ok = 0;
        }
        g_is64 = ok;
    }
}

// ---------------- CSR build ----------------
__global__ void k_hist(const void* ei) {
    int i = blockIdx.x * blockDim.x + threadIdx.x;
    if (i >= EP) return;
    int is64 = g_is64;
    int d = (i < EE) ? eidx(ei, (long long)EE + i, is64) : (i - EE);
    atomicAdd(&g_counts[d], 1);
}

__global__ void k_scan1() {   // per-block sums (196 blocks x 256)
    __shared__ int s[256];
    int t = threadIdx.x;
    int i = blockIdx.x * 256 + t;
    s[t] = (i < NN) ? g_counts[i] : 0;
    __syncthreads();
    for (int o = 128; o > 0; o >>= 1) {
        if (t < o) s[t] += s[t + o];
        __syncthreads();
    }
    if (t == 0) g_bsums[blockIdx.x] = s[0];
}

__global__ void k_scan2() {   // single block: exclusive scan of 196 block sums
    __shared__ int s[256];
    int t = threadIdx.x;
    int v = (t < 196) ? g_bsums[t] : 0;
    s[t] = v;
    __syncthreads();
    for (int o = 1; o < 256; o <<= 1) {
        int x = (t >= o) ? s[t - o] : 0;
        __syncthreads();
        s[t] += x;
        __syncthreads();
    }
    g_bsums[t] = s[t] - v;    // exclusive
}

__global__ void k_scan3() {   // rowptr = block offset + intra-block exclusive
    __shared__ int s[256];
    int t = threadIdx.x;
    int i = blockIdx.x * 256 + t;
    int v = (i < NN) ? g_counts[i] : 0;
    s[t] = v;
    __syncthreads();
    for (int o = 1; o < 256; o <<= 1) {
        int x = (t >= o) ? s[t - o] : 0;
        __syncthreads();
        s[t] += x;
        __syncthreads();
    }
    int excl = s[t] - v + g_bsums[blockIdx.x];
    if (i < NN) { g_rowptr[i] = excl; g_cursor[i] = excl; }
    if (i == 0) g_rowptr[NN] = EP;
}

__global__ void k_scatter(const void* ei) {
    int i = blockIdx.x * blockDim.x + threadIdx.x;
    if (i >= EP) return;
    int is64 = g_is64;
    int s, d;
    if (i < EE) {
        s = eidx(ei, i, is64);
        d = eidx(ei, (long long)EE + i, is64);
    } else {
        s = d = i - EE;
    }
    int pos = atomicAdd(&g_cursor[d], 1);
    g_esrc[pos] = s;
}

// ---------------- GEMM1: h1 = x @ W1  [50000,128]x[128,256] fp32 --------------
// 128x64 block tile, 8x4 per thread, 256 threads, K-chunks of 16.
__global__ void k_gemm1(const float* __restrict__ A, const float* __restrict__ B) {
    __shared__ float As[16][128];
    __shared__ float Bs[16][64];
    int tid = threadIdx.x;
    int bx = blockIdx.x, by = blockIdx.y;
    int row0 = by * 128;
    int am = tid >> 1;              // 0..127: A row within tile
    int ak = (tid & 1) * 8;         // 0 or 8: A col group (2 float4)
    int bk = tid >> 4;              // 0..15
    int bn = (tid & 15) * 4;        // 0..60
    int tx = tid & 15, ty = tid >> 4;
    float acc[8][4] = {};
    for (int k0 = 0; k0 < KIN; k0 += 16) {
        float4 a0 = make_float4(0.f, 0.f, 0.f, 0.f);
        float4 a1 = make_float4(0.f, 0.f, 0.f, 0.f);
        int gr = row0 + am;
        if (gr < NN) {
            a0 = *(const float4*)(A + (size_t)gr * KIN + k0 + ak);
            a1 = *(const float4*)(A + (size_t)gr * KIN + k0 + ak + 4);
        }
        As[ak + 0][am] = a0.x; As[ak + 1][am] = a0.y;
        As[ak + 2][am] = a0.z; As[ak + 3][am] = a0.w;
        As[ak + 4][am] = a1.x; As[ak + 5][am] = a1.y;
        As[ak + 6][am] = a1.z; As[ak + 7][am] = a1.w;
        *(float4*)&Bs[bk][bn] =
            *(const float4*)(B + (size_t)(k0 + bk) * C1 + bx * 64 + bn);
        __syncthreads();
#pragma unroll
        for (int k = 0; k < 16; k++) {
            float4 b  = *(const float4*)&Bs[k][tx << 2];
            float4 aA = *(const float4*)&As[k][ty << 3];
            float4 aB = *(const float4*)&As[k][(ty << 3) + 4];
            acc[0][0] += aA.x * b.x; acc[0][1] += aA.x * b.y; acc[0][2] += aA.x * b.z; acc[0][3] += aA.x * b.w;
            acc[1][0] += aA.y * b.x; acc[1][1] += aA.y * b.y; acc[1][2] += aA.y * b.z; acc[1][3] += aA.y * b.w;
            acc[2][0] += aA.z * b.x; acc[2][1] += aA.z * b.y; acc[2][2] += aA.z * b.z; acc[2][3] += aA.z * b.w;
            acc[3][0] += aA.w * b.x; acc[3][1] += aA.w * b.y; acc[3][2] += aA.w * b.z; acc[3][3] += aA.w * b.w;
            acc[4][0] += aB.x * b.x; acc[4][1] += aB.x * b.y; acc[4][2] += aB.x * b.z; acc[4][3] += aB.x * b.w;
            acc[5][0] += aB.y * b.x; acc[5][1] += aB.y * b.y; acc[5][2] += aB.y * b.z; acc[5][3] += aB.y * b.w;
            acc[6][0] += aB.z * b.x; acc[6][1] += aB.z * b.y; acc[6][2] += aB.z * b.z; acc[6][3] += aB.z * b.w;
            acc[7][0] += aB.w * b.x; acc[7][1] += aB.w * b.y; acc[7][2] += aB.w * b.z; acc[7][3] += aB.w * b.w;
        }
        __syncthreads();
    }
    int gc = bx * 64 + (tx << 2);
#pragma unroll
    for (int i = 0; i < 8; i++) {
        int gr = row0 + (ty << 3) + i;
        if (gr < NN)
            *(float4*)(g_h1 + (size_t)gr * C1 + gc) =
                make_float4(acc[i][0], acc[i][1], acc[i][2], acc[i][3]);
    }
}

// ---------------- attention logits per (node, head) ----------------
__global__ void k_asd1(const float* __restrict__ asrc, const float* __restrict__ adst) {
    int tid = blockIdx.x * blockDim.x + threadIdx.x;
    if (tid >= NN * NH) return;
    int n = tid >> 3, h = tid & 7;
    const float4* hp = (const float4*)(g_h1 + (size_t)n * C1 + h * HD);
    const float4* sp = (const float4*)(asrc + h * HD);
    const float4* dp = (const float4*)(adst + h * HD);
    float s = 0.f, d = 0.f;
#pragma unroll
    for (int q = 0; q < 8; q++) {
        float4 a = hp[q], b = sp[q], c = dp[q];
        s += a.x * b.x + a.y * b.y + a.z * b.z + a.w * b.w;
        d += a.x * c.x + a.y * c.y + a.z * c.z + a.w * c.w;
    }
    g_as1[tid] = s;
    g_ad1[tid] = d;
}

// ---------------- layer-1 aggregation: warp per dst node, no atomics ----------
// Single pass: softmax shift m=0 (shift-invariant; logits are O(7) max, exp safe).
// Lane t owns channels [t*4,t*4+4) (head t/8) and [128+t*4,...) (head 4+t/8).
__global__ void k_agg1(const float* __restrict__ b1) {
    int warp = (blockIdx.x * blockDim.x + threadIdx.x) >> 5;
    if (warp >= NN) return;
    int lane = threadIdx.x & 31;
    int n = warp;
    int hA = lane >> 3, hB = 4 + (lane >> 3);
    int beg = g_rowptr[n], end = g_rowptr[n + 1];
    float adA = g_ad1[n * NH + hA], adB = g_ad1[n * NH + hB];

    float4 acc0 = make_float4(0.f, 0.f, 0.f, 0.f);
    float4 acc1 = make_float4(0.f, 0.f, 0.f, 0.f);
    float dA = 0.f, dB = 0.f;
    int i = beg;
    for (; i + 1 < end; i += 2) {
        int s0 = g_esrc[i], s1 = g_esrc[i + 1];
        const float4* hp0 = (const float4*)(g_h1 + (size_t)s0 * C1);
        const float4* hp1 = (const float4*)(g_h1 + (size_t)s1 * C1);
        float eA0 = lrelu(g_as1[s0 * NH + hA] + adA);
        float eB0 = lrelu(g_as1[s0 * NH + hB] + adB);
        float eA1 = lrelu(g_as1[s1 * NH + hA] + adA);
        float eB1 = lrelu(g_as1[s1 * NH + hB] + adB);
        float4 u0 = hp0[lane], u1 = hp0[32 + lane];
        float4 v0 = hp1[lane], v1 = hp1[32 + lane];
        float wA0 = __expf(eA0), wB0 = __expf(eB0);
        float wA1 = __expf(eA1), wB1 = __expf(eB1);
        dA += wA0 + wA1; dB += wB0 + wB1;
        acc0.x += wA0 * u0.x + wA1 * v0.x; acc0.y += wA0 * u0.y + wA1 * v0.y;
        acc0.z += wA0 * u0.z + wA1 * v0.z; acc0.w += wA0 * u0.w + wA1 * v0.w;
        acc1.x += wB0 * u1.x + wB1 * v1.x; acc1.y += wB0 * u1.y + wB1 * v1.y;
        acc1.z += wB0 * u1.z + wB1 * v1.z; acc1.w += wB0 * u1.w + wB1 * v1.w;
    }
    for (; i < end; i++) {
        int s = g_esrc[i];
        float wA = __expf(lrelu(g_as1[s * NH + hA] + adA));
        float wB = __expf(lrelu(g_as1[s * NH + hB] + adB));
        dA += wA; dB += wB;
        const float4* hp = (const float4*)(g_h1 + (size_t)s * C1);
        float4 v0 = hp[lane];
        float4 v1 = hp[32 + lane];
        acc0.x += wA * v0.x; acc0.y += wA * v0.y; acc0.z += wA * v0.z; acc0.w += wA * v0.w;
        acc1.x += wB * v1.x; acc1.y += wB * v1.y; acc1.z += wB * v1.z; acc1.w += wB * v1.w;
    }
    float iA = 1.f / dA, iB = 1.f / dB;
    const float4* bp = (const float4*)b1;
    float4 bb0 = bp[lane], bb1 = bp[32 + lane];
    float4 o0, o1;
    o0.x = elu1(acc0.x * iA + bb0.x); o0.y = elu1(acc0.y * iA + bb0.y);
    o0.z = elu1(acc0.z * iA + bb0.z); o0.w = elu1(acc0.w * iA + bb0.w);
    o1.x = elu1(acc1.x * iB + bb1.x); o1.y = elu1(acc1.y * iB + bb1.y);
    o1.z = elu1(acc1.z * iB + bb1.z); o1.w = elu1(acc1.w * iB + bb1.w);
    float4* op = (float4*)(g_h1out + (size_t)n * C1);
    op[lane] = o0;
    op[32 + lane] = o1;
}

// ---------------- fold att2 into W2: [256,12] = [W2 | W2@as2 | W2@ad2] --------
__global__ void k_w2aug(const float* __restrict__ W2,
                        const float* __restrict__ as2,
                        const float* __restrict__ ad2) {
    int k = blockIdx.x * blockDim.x + threadIdx.x;
    if (k >= C1) return;
    float s = 0.f, d = 0.f;
#pragma unroll
    for (int c = 0; c < NC; c++) {
        float w = W2[k * NC + c];
        g_w2aug[k * 12 + c] = w;
        s += w * as2[c];
        d += w * ad2[c];
    }
    g_w2aug[k * 12 + 10] = s;
    g_w2aug[k * 12 + 11] = d;
}

// ---------------- GEMM2: h2 = h1out @ W2aug  [50000,256]x[256,12] -------------
__global__ void k_gemm2() {
    __shared__ float Ws[C1 * 12];
    for (int i = threadIdx.x; i < C1 * 12; i += blockDim.x) Ws[i] = g_w2aug[i];
    __syncthreads();
    int n = blockIdx.x * blockDim.x + threadIdx.x;
    if (n >= NN) return;
    float acc[12];
#pragma unroll
    for (int c = 0; c < 12; c++) acc[c] = 0.f;
    const float4* xp = (const float4*)(g_h1out + (size_t)n * C1);
    for (int q = 0; q < 64; q++) {
        float4 x = xp[q];
        const float* w = &Ws[(q * 4) * 12];
#pragma unroll
        for (int c = 0; c < 12; c++)
            acc[c] += x.x * w[c] + x.y * w[12 + c] + x.z * w[24 + c] + x.w * w[36 + c];
    }
#pragma unroll
    for (int c = 0; c < 12; c++) g_h2[n * 12 + c] = acc[c];
}

// ---------------- layer-2 agg + log-softmax: warp/node, edge-parallel lanes ---
__global__ void k_agg2(const float* __restrict__ b2, float* __restrict__ out) {
    int warp = (blockIdx.x * blockDim.x + threadIdx.x) >> 5;
    if (warp >= NN) return;
    int lane = threadIdx.x & 31;
    int n = warp;
    float ad2v = g_h2[n * 12 + 11];
    int beg = g_rowptr[n], end = g_rowptr[n + 1];

    float4 A = make_float4(0.f, 0.f, 0.f, 0.f);   // classes 0-3
    float4 Bv = make_float4(0.f, 0.f, 0.f, 0.f);  // classes 4-7
    float c8 = 0.f, c9 = 0.f, den = 0.f;
    for (int i = beg + lane; i < end; i += 32) {
        int s = g_esrc[i];
        const float4* hp = (const float4*)(g_h2 + (size_t)s * 12);
        float4 r0 = hp[0], r1 = hp[1], r2 = hp[2];
        float w = __expf(lrelu(r2.z + ad2v));     // r2.z = a_s2[src]; shift m=0
        den += w;
        A.x += w * r0.x; A.y += w * r0.y; A.z += w * r0.z; A.w += w * r0.w;
        Bv.x += w * r1.x; Bv.y += w * r1.y; Bv.z += w * r1.z; Bv.w += w * r1.w;
        c8 += w * r2.x; c9 += w * r2.y;
    }
#pragma unroll
    for (int o = 16; o > 0; o >>= 1) {
        A.x += __shfl_xor_sync(0xffffffffu, A.x, o);
        A.y += __shfl_xor_sync(0xffffffffu, A.y, o);
        A.z += __shfl_xor_sync(0xffffffffu, A.z, o);
        A.w += __shfl_xor_sync(0xffffffffu, A.w, o);
        Bv.x += __shfl_xor_sync(0xffffffffu, Bv.x, o);
        Bv.y += __shfl_xor_sync(0xffffffffu, Bv.y, o);
        Bv.z += __shfl_xor_sync(0xffffffffu, Bv.z, o);
        Bv.w += __shfl_xor_sync(0xffffffffu, Bv.w, o);
        c8  += __shfl_xor_sync(0xffffffffu, c8, o);
        c9  += __shfl_xor_sync(0xffffffffu, c9, o);
        den += __shfl_xor_sync(0xffffffffu, den, o);
    }
    if (lane == 0) {
        float inv = 1.f / den;
        float v[NC];
        v[0] = A.x * inv + b2[0]; v[1] = A.y * inv + b2[1];
        v[2] = A.z * inv + b2[2]; v[3] = A.w * inv + b2[3];
        v[4] = Bv.x * inv + b2[4]; v[5] = Bv.y * inv + b2[5];
        v[6] = Bv.z * inv + b2[6]; v[7] = Bv.w * inv + b2[7];
        v[8] = c8 * inv + b2[8];  v[9] = c9 * inv + b2[9];
        float mx = v[0];
#pragma unroll
        for (int c = 1; c < NC; c++) mx = fmaxf(mx, v[c]);
        float sm = 0.f;
#pragma unroll
        for (int c = 0; c < NC; c++) sm += __expf(v[c] - mx);
        float l = mx + __logf(sm);
#pragma unroll
        for (int c = 0; c < NC; c++) out[(size_t)n * NC + c] = v[c] - l;
    }
}

// ---------------- launch ----------------
// Order puts k_gemm1 at launch slot 4 (where the ncu capture window landed).
extern "C" void kernel_launch(void* const* d_in, const int* in_sizes, int n_in,
                              void* d_out, int out_size) {
    const float* x   = (const float*)d_in[0];
    const void*  ei  = d_in[1];
    const float* W1  = (const float*)d_in[2];
    const float* as1 = (const float*)d_in[3];
    const float* ad1 = (const float*)d_in[4];
    const float* b1  = (const float*)d_in[5];
    const float* W2  = (const float*)d_in[6];
    const float* as2 = (const float*)d_in[7];
    const float* ad2 = (const float*)d_in[8];
    const float* b2  = (const float*)d_in[9];
    float* out = (float*)d_out;

    k_init<<<(NN + 255) / 256, 256>>>(ei);                 // 1
    k_hist<<<(EP + 255) / 256, 256>>>(ei);                 // 2
    k_scan1<<<196, 256>>>();                               // 3
    dim3 g1(4, (NN + 127) / 128);
    k_gemm1<<<g1, 256>>>(x, W1);                           // 4  <- ncu slot
    k_scan2<<<1, 256>>>();                                 // 5
    k_scan3<<<196, 256>>>();                               // 6
    k_scatter<<<(EP + 255) / 256, 256>>>(ei);              // 7
    k_asd1<<<(NN * NH + 255) / 256, 256>>>(as1, ad1);      // 8
    k_agg1<<<(NN + 7) / 8, 256>>>(b1);                     // 9
    k_w2aug<<<1, 256>>>(W2, as2, ad2);                     // 10
    k_gemm2<<<(NN + 127) / 128, 128>>>();                  // 11
    k_agg2<<<(NN + 7) / 8, 256>>>(b2, out);                // 12
}

// round 6
// speedup vs baseline: 1.2546x; 1.0922x over previous
#include <cuda_runtime.h>
#include <cuda_fp16.h>
#include <math.h>
#include <stdint.h>

// ---------------- problem constants ----------------
#define NN   50000
#define EE   800000
#define EP   (EE + NN)
#define KIN  128
#define C1   256              // 8 heads * 32
#define NH   8
#define HD   32
#define NC   10
#define NEG  0.2f

// ---------------- scratch globals ----------------
__device__ __align__(256) __half g_h1h[(size_t)NN * C1];       // x@W1 in fp16
__device__ __align__(256) float  g_h1out[(size_t)NN * C1];     // layer-1 out
__device__ __align__(256) float  g_as1[NN * NH];
__device__ __align__(256) float  g_ad1[NN * NH];
__device__ __align__(256) float  g_h2[NN * 12];
__device__ __align__(256) float  g_w2aug[C1 * 12];
__device__ __align__(256) __half g_Whi[C1 * KIN];              // W1^T hi  [n][k]
__device__ __align__(256) __half g_Wlo[C1 * KIN];              // W1^T lo  [n][k]
__device__ __align__(256) int    g_rowptr[NN + 1];
__device__ __align__(256) int    g_cursor[NN];
__device__ __align__(256) int    g_counts[NN];
__device__ __align__(256) int    g_esrc[EP];
__device__ __align__(256) int    g_bsums[256];
__device__ int g_is64;

// ---------------- small helpers ----------------
__device__ __forceinline__ int eidx(const void* p, long long i, int is64) {
    return is64 ? (int)((const long long*)p)[i] : ((const int*)p)[i];
}
__device__ __forceinline__ float lrelu(float x) { return x > 0.f ? x : NEG * x; }
__device__ __forceinline__ float elu1(float x)  { return x > 0.f ? x : (__expf(x) - 1.f); }

// ---------------- init: zero counts + dtype sniff ----------------------------
__global__ void k_init(const void* ei) {
    int i = blockIdx.x * blockDim.x + threadIdx.x;
    if (i < NN) g_counts[i] = 0;
    if (i == 0) {
        const long long* p = (const long long*)ei;
        int ok = 1;
        for (int q = 0; q < 64; q++) {
            long long v = p[q];
            if (v < 0 || v >= NN) ok = 0;
        }
        g_is64 = ok;
    }
}

// ---------------- CSR build ----------------
__global__ void k_hist(const void* ei) {
    int i = blockIdx.x * blockDim.x + threadIdx.x;
    if (i >= EP) return;
    int is64 = g_is64;
    int d = (i < EE) ? eidx(ei, (long long)EE + i, is64) : (i - EE);
    atomicAdd(&g_counts[d], 1);
}

__global__ void k_scan1() {
    __shared__ int s[256];
    int t = threadIdx.x;
    int i = blockIdx.x * 256 + t;
    s[t] = (i < NN) ? g_counts[i] : 0;
    __syncthreads();
    for (int o = 128; o > 0; o >>= 1) {
        if (t < o) s[t] += s[t + o];
        __syncthreads();
    }
    if (t == 0) g_bsums[blockIdx.x] = s[0];
}

__global__ void k_scan2() {
    __shared__ int s[256];
    int t = threadIdx.x;
    int v = (t < 196) ? g_bsums[t] : 0;
    s[t] = v;
    __syncthreads();
    for (int o = 1; o < 256; o <<= 1) {
        int x = (t >= o) ? s[t - o] : 0;
        __syncthreads();
        s[t] += x;
        __syncthreads();
    }
    g_bsums[t] = s[t] - v;
}

__global__ void k_scan3() {
    __shared__ int s[256];
    int t = threadIdx.x;
    int i = blockIdx.x * 256 + t;
    int v = (i < NN) ? g_counts[i] : 0;
    s[t] = v;
    __syncthreads();
    for (int o = 1; o < 256; o <<= 1) {
        int x = (t >= o) ? s[t - o] : 0;
        __syncthreads();
        s[t] += x;
        __syncthreads();
    }
    int excl = s[t] - v + g_bsums[blockIdx.x];
    if (i < NN) { g_rowptr[i] = excl; g_cursor[i] = excl; }
    if (i == 0) g_rowptr[NN] = EP;
}

__global__ void k_scatter(const void* ei) {
    int i = blockIdx.x * blockDim.x + threadIdx.x;
    if (i >= EP) return;
    int is64 = g_is64;
    int s, d;
    if (i < EE) {
        s = eidx(ei, i, is64);
        d = eidx(ei, (long long)EE + i, is64);
    } else {
        s = d = i - EE;
    }
    int pos = atomicAdd(&g_cursor[d], 1);
    g_esrc[pos] = s;
}

// ---------------- prep: W1 -> transposed fp16 hi/lo splits --------------------
__global__ void k_prepB(const float* __restrict__ W1) {
    int i = blockIdx.x * blockDim.x + threadIdx.x;
    if (i >= KIN * C1) return;
    int k = i >> 8, n = i & 255;
    float v = W1[i];                       // W1[k][n] row-major
    __half hi = __float2half(v);
    __half lo = __float2half(v - __half2float(hi));
    g_Whi[n * KIN + k] = hi;
    g_Wlo[n * KIN + k] = lo;
}

// ---------------- GEMM1 via mma.sync fp16 hi/lo: h1h = fp16(x @ W1) ----------
// CTA: 128 thr (2x2 warps), tile 64(M) x 64(N), K=128 fully resident in SMEM.
// SMEM stride 136 halves -> conflict-free fragment loads.
#define SAS 136
#define OFF_AHI 0
#define OFF_ALO (64 * SAS)
#define OFF_BHI (2 * 64 * SAS)
#define OFF_BLO (3 * 64 * SAS)
#define SM_HALVES (4 * 64 * SAS)

__device__ __forceinline__ void lda_frag(uint32_t a[4], const __half* s, int row0, int k0, int lane) {
    int r = row0 + (lane >> 2), c = k0 + (lane & 3) * 2;
    a[0] = *(const uint32_t*)(s + r * SAS + c);
    a[1] = *(const uint32_t*)(s + (r + 8) * SAS + c);
    a[2] = *(const uint32_t*)(s + r * SAS + c + 8);
    a[3] = *(const uint32_t*)(s + (r + 8) * SAS + c + 8);
}
__device__ __forceinline__ void ldb_frag(uint32_t b[2], const __half* s, int n0, int k0, int lane) {
    int n = n0 + (lane >> 2), k = k0 + (lane & 3) * 2;
    b[0] = *(const uint32_t*)(s + n * SAS + k);
    b[1] = *(const uint32_t*)(s + n * SAS + k + 8);
}
__device__ __forceinline__ void mma16816(float c[4], const uint32_t a[4], const uint32_t b[2]) {
    asm volatile(
        "mma.sync.aligned.m16n8k16.row.col.f32.f16.f16.f32 "
        "{%0,%1,%2,%3},{%4,%5,%6,%7},{%8,%9},{%0,%1,%2,%3};"
        : "+f"(c[0]), "+f"(c[1]), "+f"(c[2]), "+f"(c[3])
        : "r"(a[0]), "r"(a[1]), "r"(a[2]), "r"(a[3]), "r"(b[0]), "r"(b[1]));
}

__global__ void __launch_bounds__(128) k_hmma1(const float* __restrict__ x) {
    extern __shared__ __half sm[];
    int tid = threadIdx.x;
    int wid = tid >> 5, lane = tid & 31;
    int wm = wid >> 1, wn = wid & 1;           // 2x2 warp grid, 32x32 each
    int row0 = blockIdx.x * 64;
    int col0 = blockIdx.y * 64;

    // ---- load A: x[row0..row0+63][0..127] fp32 -> fp16 hi/lo ----
    for (int i = tid; i < 2048; i += 128) {    // 64 rows x 32 float4
        int r = i >> 5, c = (i & 31) * 4;
        int gr = row0 + r;
        float4 v = make_float4(0.f, 0.f, 0.f, 0.f);
        if (gr < NN) v = *(const float4*)(x + (size_t)gr * KIN + c);
        __half h0 = __float2half(v.x), h1 = __float2half(v.y);
        __half h2 = __float2half(v.z), h3 = __float2half(v.w);
        __half l0 = __float2half(v.x - __half2float(h0));
        __half l1 = __float2half(v.y - __half2float(h1));
        __half l2 = __float2half(v.z - __half2float(h2));
        __half l3 = __float2half(v.w - __half2float(h3));
        __half* ah = sm + OFF_AHI + r * SAS + c;
        __half* al = sm + OFF_ALO + r * SAS + c;
        ah[0] = h0; ah[1] = h1; ah[2] = h2; ah[3] = h3;
        al[0] = l0; al[1] = l1; al[2] = l2; al[3] = l3;
    }
    // ---- load B: W^T[col0..col0+63][0..127] fp16 hi/lo (prepped) ----
    for (int i = tid; i < 1024; i += 128) {    // 64 n x 16 uint4(8 halves)
        int n = i >> 4, k8 = (i & 15) * 8;
        uint4 hv = *(const uint4*)(g_Whi + (size_t)(col0 + n) * KIN + k8);
        uint4 lv = *(const uint4*)(g_Wlo + (size_t)(col0 + n) * KIN + k8);
        *(uint4*)(sm + OFF_BHI + n * SAS + k8) = hv;
        *(uint4*)(sm + OFF_BLO + n * SAS + k8) = lv;
    }
    __syncthreads();

    float acc[2][4][4] = {};
#pragma unroll
    for (int ks = 0; ks < 8; ks++) {
        int k0 = ks * 16;
        uint32_t ah[2][4], al[2][4], bh[4][2], bl[4][2];
#pragma unroll
        for (int mt = 0; mt < 2; mt++) {
            lda_frag(ah[mt], sm + OFF_AHI, wm * 32 + mt * 16, k0, lane);
            lda_frag(al[mt], sm + OFF_ALO, wm * 32 + mt * 16, k0, lane);
        }
#pragma unroll
        for (int nt = 0; nt < 4; nt++) {
            ldb_frag(bh[nt], sm + OFF_BHI, wn * 32 + nt * 8, k0, lane);
            ldb_frag(bl[nt], sm + OFF_BLO, wn * 32 + nt * 8, k0, lane);
        }
#pragma unroll
        for (int mt = 0; mt < 2; mt++)
#pragma unroll
            for (int nt = 0; nt < 4; nt++) {
                mma16816(acc[mt][nt], ah[mt], bh[nt]);
                mma16816(acc[mt][nt], al[mt], bh[nt]);
                mma16816(acc[mt][nt], ah[mt], bl[nt]);
            }
    }

    // ---- store fp16 h1 ----
#pragma unroll
    for (int mt = 0; mt < 2; mt++) {
        int r = row0 + wm * 32 + mt * 16 + (lane >> 2);
#pragma unroll
        for (int nt = 0; nt < 4; nt++) {
            int gc = col0 + wn * 32 + nt * 8 + (lane & 3) * 2;
            if (r < NN)
                *(__half2*)(g_h1h + (size_t)r * C1 + gc) =
                    __floats2half2_rn(acc[mt][nt][0], acc[mt][nt][1]);
            if (r + 8 < NN)
                *(__half2*)(g_h1h + (size_t)(r + 8) * C1 + gc) =
                    __floats2half2_rn(acc[mt][nt][2], acc[mt][nt][3]);
        }
    }
}

// ---------------- attention logits per (node, head), fp16 h1 -----------------
__global__ void k_asd1(const float* __restrict__ asrc, const float* __restrict__ adst) {
    int tid = blockIdx.x * blockDim.x + threadIdx.x;
    if (tid >= NN * NH) return;
    int n = tid >> 3, h = tid & 7;
    const __half2* hp = (const __half2*)(g_h1h + (size_t)n * C1 + h * HD);
    const float* sa = asrc + h * HD;
    const float* da = adst + h * HD;
    float s = 0.f, d = 0.f;
#pragma unroll
    for (int q = 0; q < 16; q++) {
        float2 f = __half22float2(hp[q]);
        s += f.x * sa[2 * q] + f.y * sa[2 * q + 1];
        d += f.x * da[2 * q] + f.y * da[2 * q + 1];
    }
    g_as1[tid] = s;
    g_ad1[tid] = d;
}

// ---------------- layer-1 aggregation: warp/node, fp16 gather, m=0 softmax ---
__global__ void k_agg1(const float* __restrict__ b1) {
    int warp = (blockIdx.x * blockDim.x + threadIdx.x) >> 5;
    if (warp >= NN) return;
    int lane = threadIdx.x & 31;
    int n = warp;
    int hA = lane >> 3, hB = 4 + (lane >> 3);
    int beg = g_rowptr[n], end = g_rowptr[n + 1];
    float adA = g_ad1[n * NH + hA], adB = g_ad1[n * NH + hB];

    float4 acc0 = make_float4(0.f, 0.f, 0.f, 0.f);
    float4 acc1 = make_float4(0.f, 0.f, 0.f, 0.f);
    float dA = 0.f, dB = 0.f;
    int i = beg;
    for (; i + 1 < end; i += 2) {
        int s0 = g_esrc[i], s1 = g_esrc[i + 1];
        const uint2* p0 = (const uint2*)(g_h1h + (size_t)s0 * C1);
        const uint2* p1 = (const uint2*)(g_h1h + (size_t)s1 * C1);
        float eA0 = lrelu(g_as1[s0 * NH + hA] + adA);
        float eB0 = lrelu(g_as1[s0 * NH + hB] + adB);
        float eA1 = lrelu(g_as1[s1 * NH + hA] + adA);
        float eB1 = lrelu(g_as1[s1 * NH + hB] + adB);
        uint2 ua = p0[lane], ub = p0[32 + lane];
        uint2 va = p1[lane], vb = p1[32 + lane];
        float wA0 = __expf(eA0), wB0 = __expf(eB0);
        float wA1 = __expf(eA1), wB1 = __expf(eB1);
        dA += wA0 + wA1; dB += wB0 + wB1;
        {
            __half2* h = (__half2*)&ua;
            float2 f0 = __half22float2(h[0]), f1 = __half22float2(h[1]);
            acc0.x += wA0 * f0.x; acc0.y += wA0 * f0.y;
            acc0.z += wA0 * f1.x; acc0.w += wA0 * f1.y;
        }
        {
            __half2* h = (__half2*)&ub;
            float2 f0 = __half22float2(h[0]), f1 = __half22float2(h[1]);
            acc1.x += wB0 * f0.x; acc1.y += wB0 * f0.y;
            acc1.z += wB0 * f1.x; acc1.w += wB0 * f1.y;
        }
        {
            __half2* h = (__half2*)&va;
            float2 f0 = __half22float2(h[0]), f1 = __half22float2(h[1]);
            acc0.x += wA1 * f0.x; acc0.y += wA1 * f0.y;
            acc0.z += wA1 * f1.x; acc0.w += wA1 * f1.y;
        }
        {
            __half2* h = (__half2*)&vb;
            float2 f0 = __half22float2(h[0]), f1 = __half22float2(h[1]);
            acc1.x += wB1 * f0.x; acc1.y += wB1 * f0.y;
            acc1.z += wB1 * f1.x; acc1.w += wB1 * f1.y;
        }
    }
    for (; i < end; i++) {
        int s = g_esrc[i];
        const uint2* p = (const uint2*)(g_h1h + (size_t)s * C1);
        float wA = __expf(lrelu(g_as1[s * NH + hA] + adA));
        float wB = __expf(lrelu(g_as1[s * NH + hB] + adB));
        dA += wA; dB += wB;
        uint2 ua = p[lane], ub = p[32 + lane];
        __half2* h0 = (__half2*)&ua;
        __half2* h1 = (__half2*)&ub;
        float2 f0 = __half22float2(h0[0]), f1 = __half22float2(h0[1]);
        float2 f2 = __half22float2(h1[0]), f3 = __half22float2(h1[1]);
        acc0.x += wA * f0.x; acc0.y += wA * f0.y; acc0.z += wA * f1.x; acc0.w += wA * f1.y;
        acc1.x += wB * f2.x; acc1.y += wB * f2.y; acc1.z += wB * f3.x; acc1.w += wB * f3.y;
    }
    float iA = 1.f / dA, iB = 1.f / dB;
    const float4* bp = (const float4*)b1;
    float4 bb0 = bp[lane], bb1 = bp[32 + lane];
    float4 o0, o1;
    o0.x = elu1(acc0.x * iA + bb0.x); o0.y = elu1(acc0.y * iA + bb0.y);
    o0.z = elu1(acc0.z * iA + bb0.z); o0.w = elu1(acc0.w * iA + bb0.w);
    o1.x = elu1(acc1.x * iB + bb1.x); o1.y = elu1(acc1.y * iB + bb1.y);
    o1.z = elu1(acc1.z * iB + bb1.z); o1.w = elu1(acc1.w * iB + bb1.w);
    float4* op = (float4*)(g_h1out + (size_t)n * C1);
    op[lane] = o0;
    op[32 + lane] = o1;
}

// ---------------- fold att2 into W2 ----------------
__global__ void k_w2aug(const float* __restrict__ W2,
                        const float* __restrict__ as2,
                        const float* __restrict__ ad2) {
    int k = blockIdx.x * blockDim.x + threadIdx.x;
    if (k >= C1) return;
    float s = 0.f, d = 0.f;
#pragma unroll
    for (int c = 0; c < NC; c++) {
        float w = W2[k * NC + c];
        g_w2aug[k * 12 + c] = w;
        s += w * as2[c];
        d += w * ad2[c];
    }
    g_w2aug[k * 12 + 10] = s;
    g_w2aug[k * 12 + 11] = d;
}

// ---------------- GEMM2: h2 = h1out @ W2aug ----------------
__global__ void k_gemm2() {
    __shared__ float Ws[C1 * 12];
    for (int i = threadIdx.x; i < C1 * 12; i += blockDim.x) Ws[i] = g_w2aug[i];
    __syncthreads();
    int n = blockIdx.x * blockDim.x + threadIdx.x;
    if (n >= NN) return;
    float acc[12];
#pragma unroll
    for (int c = 0; c < 12; c++) acc[c] = 0.f;
    const float4* xp = (const float4*)(g_h1out + (size_t)n * C1);
    for (int q = 0; q < 64; q++) {
        float4 x = xp[q];
        const float* w = &Ws[(q * 4) * 12];
#pragma unroll
        for (int c = 0; c < 12; c++)
            acc[c] += x.x * w[c] + x.y * w[12 + c] + x.z * w[24 + c] + x.w * w[36 + c];
    }
#pragma unroll
    for (int c = 0; c < 12; c++) g_h2[n * 12 + c] = acc[c];
}

// ---------------- layer-2 agg + log-softmax ----------------
__global__ void k_agg2(const float* __restrict__ b2, float* __restrict__ out) {
    int warp = (blockIdx.x * blockDim.x + threadIdx.x) >> 5;
    if (warp >= NN) return;
    int lane = threadIdx.x & 31;
    int n = warp;
    float ad2v = g_h2[n * 12 + 11];
    int beg = g_rowptr[n], end = g_rowptr[n + 1];

    float4 A = make_float4(0.f, 0.f, 0.f, 0.f);
    float4 Bv = make_float4(0.f, 0.f, 0.f, 0.f);
    float c8 = 0.f, c9 = 0.f, den = 0.f;
    for (int i = beg + lane; i < end; i += 32) {
        int s = g_esrc[i];
        const float4* hp = (const float4*)(g_h2 + (size_t)s * 12);
        float4 r0 = hp[0], r1 = hp[1], r2 = hp[2];
        float w = __expf(lrelu(r2.z + ad2v));
        den += w;
        A.x += w * r0.x; A.y += w * r0.y; A.z += w * r0.z; A.w += w * r0.w;
        Bv.x += w * r1.x; Bv.y += w * r1.y; Bv.z += w * r1.z; Bv.w += w * r1.w;
        c8 += w * r2.x; c9 += w * r2.y;
    }
#pragma unroll
    for (int o = 16; o > 0; o >>= 1) {
        A.x += __shfl_xor_sync(0xffffffffu, A.x, o);
        A.y += __shfl_xor_sync(0xffffffffu, A.y, o);
        A.z += __shfl_xor_sync(0xffffffffu, A.z, o);
        A.w += __shfl_xor_sync(0xffffffffu, A.w, o);
        Bv.x += __shfl_xor_sync(0xffffffffu, Bv.x, o);
        Bv.y += __shfl_xor_sync(0xffffffffu, Bv.y, o);
        Bv.z += __shfl_xor_sync(0xffffffffu, Bv.z, o);
        Bv.w += __shfl_xor_sync(0xffffffffu, Bv.w, o);
        c8  += __shfl_xor_sync(0xffffffffu, c8, o);
        c9  += __shfl_xor_sync(0xffffffffu, c9, o);
        den += __shfl_xor_sync(0xffffffffu, den, o);
    }
    if (lane == 0) {
        float inv = 1.f / den;
        float v[NC];
        v[0] = A.x * inv + b2[0]; v[1] = A.y * inv + b2[1];
        v[2] = A.z * inv + b2[2]; v[3] = A.w * inv + b2[3];
        v[4] = Bv.x * inv + b2[4]; v[5] = Bv.y * inv + b2[5];
        v[6] = Bv.z * inv + b2[6]; v[7] = Bv.w * inv + b2[7];
        v[8] = c8 * inv + b2[8];  v[9] = c9 * inv + b2[9];
        float mx = v[0];
#pragma unroll
        for (int c = 1; c < NC; c++) mx = fmaxf(mx, v[c]);
        float sm = 0.f;
#pragma unroll
        for (int c = 0; c < NC; c++) sm += __expf(v[c] - mx);
        float l = mx + __logf(sm);
#pragma unroll
        for (int c = 0; c < NC; c++) out[(size_t)n * NC + c] = v[c] - l;
    }
}

// ---------------- launch ----------------
extern "C" void kernel_launch(void* const* d_in, const int* in_sizes, int n_in,
                              void* d_out, int out_size) {
    const float* x   = (const float*)d_in[0];
    const void*  ei  = d_in[1];
    const float* W1  = (const float*)d_in[2];
    const float* as1 = (const float*)d_in[3];
    const float* ad1 = (const float*)d_in[4];
    const float* b1  = (const float*)d_in[5];
    const float* W2  = (const float*)d_in[6];
    const float* as2 = (const float*)d_in[7];
    const float* ad2 = (const float*)d_in[8];
    const float* b2  = (const float*)d_in[9];
    float* out = (float*)d_out;

    int smem_bytes = SM_HALVES * (int)sizeof(__half);   // ~69.6 KB
    cudaFuncSetAttribute(k_hmma1, cudaFuncAttributeMaxDynamicSharedMemorySize, smem_bytes);

    k_init<<<(NN + 255) / 256, 256>>>(ei);                  // 1
    k_hist<<<(EP + 255) / 256, 256>>>(ei);                  // 2
    k_prepB<<<(KIN * C1 + 255) / 256, 256>>>(W1);           // 3
    dim3 gg((NN + 63) / 64, 4);
    k_hmma1<<<gg, 128, smem_bytes>>>(x);                    // 4 <- ncu slot
    k_scan1<<<196, 256>>>();                                // 5
    k_scan2<<<1, 256>>>();                                  // 6
    k_scan3<<<196, 256>>>();                                // 7
    k_scatter<<<(EP + 255) / 256, 256>>>(ei);               // 8
    k_asd1<<<(NN * NH + 255) / 256, 256>>>(as1, ad1);       // 9
    k_agg1<<<(NN + 7) / 8, 256>>>(b1);                      // 10
    k_w2aug<<<1, 256>>>(W2, as2, ad2);                      // 11
    k_gemm2<<<(NN + 127) / 128, 128>>>();                   // 12
    k_agg2<<<(NN + 7) / 8, 256>>>(b2, out);                 // 13
}

// round 7
// speedup vs baseline: 1.3316x; 1.0614x over previous
#include <cuda_runtime.h>
#include <cuda_fp16.h>
#include <math.h>
#include <stdint.h>

// ---------------- problem constants ----------------
#define NN   50000
#define EE   800000
#define EP   (EE + NN)
#define KIN  128
#define C1   256              // 8 heads * 32
#define NH   8
#define HD   32
#define NC   10
#define NEG  0.2f

// ---------------- scratch globals ----------------
__device__ __align__(256) __half g_h1h[(size_t)NN * C1];       // x@W1 in fp16
__device__ __align__(256) float  g_h1out[(size_t)NN * C1];     // layer-1 out
__device__ __align__(256) float  g_as1[NN * NH];
__device__ __align__(256) float  g_ad1[NN * NH];
__device__ __align__(256) float  g_h2[NN * 12];
__device__ __align__(256) float  g_w2aug[C1 * 12];
__device__ __align__(256) __half g_Whi[C1 * KIN];              // W1^T hi  [n][k]
__device__ __align__(256) __half g_Wlo[C1 * KIN];              // W1^T lo  [n][k]
__device__ __align__(256) int    g_rowptr[NN + 1];
__device__ __align__(256) int    g_cursor[NN];
__device__ __align__(256) int    g_counts[NN];
__device__ __align__(256) int    g_esrc[EP];
__device__ __align__(256) int    g_bsums[256];
__device__ int g_is64;

// ---------------- small helpers ----------------
__device__ __forceinline__ int eidx(const void* p, long long i, int is64) {
    return is64 ? (int)((const long long*)p)[i] : ((const int*)p)[i];
}
__device__ __forceinline__ float lrelu(float x) { return x > 0.f ? x : NEG * x; }
__device__ __forceinline__ float elu1(float x)  { return x > 0.f ? x : (__expf(x) - 1.f); }

// ---------------- init: zero counts + dtype sniff ----------------------------
__global__ void k_init(const void* ei) {
    int i = blockIdx.x * blockDim.x + threadIdx.x;
    if (i < NN) g_counts[i] = 0;
    if (i == 0) {
        const long long* p = (const long long*)ei;
        int ok = 1;
        for (int q = 0; q < 64; q++) {
            long long v = p[q];
            if (v < 0 || v >= NN) ok = 0;
        }
        g_is64 = ok;
    }
}

// ---------------- CSR build ----------------
__global__ void k_hist(const void* ei) {
    int i = blockIdx.x * blockDim.x + threadIdx.x;
    if (i >= EP) return;
    int is64 = g_is64;
    int d = (i < EE) ? eidx(ei, (long long)EE + i, is64) : (i - EE);
    atomicAdd(&g_counts[d], 1);
}

__global__ void k_scan1() {
    __shared__ int s[256];
    int t = threadIdx.x;
    int i = blockIdx.x * 256 + t;
    s[t] = (i < NN) ? g_counts[i] : 0;
    __syncthreads();
    for (int o = 128; o > 0; o >>= 1) {
        if (t < o) s[t] += s[t + o];
        __syncthreads();
    }
    if (t == 0) g_bsums[blockIdx.x] = s[0];
}

__global__ void k_scan2() {
    __shared__ int s[256];
    int t = threadIdx.x;
    int v = (t < 196) ? g_bsums[t] : 0;
    s[t] = v;
    __syncthreads();
    for (int o = 1; o < 256; o <<= 1) {
        int x = (t >= o) ? s[t - o] : 0;
        __syncthreads();
        s[t] += x;
        __syncthreads();
    }
    g_bsums[t] = s[t] - v;
}

__global__ void k_scan3() {
    __shared__ int s[256];
    int t = threadIdx.x;
    int i = blockIdx.x * 256 + t;
    int v = (i < NN) ? g_counts[i] : 0;
    s[t] = v;
    __syncthreads();
    for (int o = 1; o < 256; o <<= 1) {
        int x = (t >= o) ? s[t - o] : 0;
        __syncthreads();
        s[t] += x;
        __syncthreads();
    }
    int excl = s[t] - v + g_bsums[blockIdx.x];
    if (i < NN) { g_rowptr[i] = excl; g_cursor[i] = excl; }
    if (i == 0) g_rowptr[NN] = EP;
}

__global__ void k_scatter(const void* ei) {
    int i = blockIdx.x * blockDim.x + threadIdx.x;
    if (i >= EP) return;
    int is64 = g_is64;
    int s, d;
    if (i < EE) {
        s = eidx(ei, i, is64);
        d = eidx(ei, (long long)EE + i, is64);
    } else {
        s = d = i - EE;
    }
    int pos = atomicAdd(&g_cursor[d], 1);
    g_esrc[pos] = s;
}

// ---------------- prep: W1 -> transposed fp16 hi/lo splits --------------------
__global__ void k_prepB(const float* __restrict__ W1) {
    int i = blockIdx.x * blockDim.x + threadIdx.x;
    if (i >= KIN * C1) return;
    int k = i >> 8, n = i & 255;
    float v = W1[i];                       // W1[k][n] row-major
    __half hi = __float2half(v);
    __half lo = __float2half(v - __half2float(hi));
    g_Whi[n * KIN + k] = hi;
    g_Wlo[n * KIN + k] = lo;
}

// ---------------- GEMM1 via mma.sync fp16 hi/lo + ldmatrix --------------------
// CTA: 256 thr (2x4 warps), tile 64(M) x 128(N), K=128 resident in SMEM.
// SMEM stride 136 halves -> conflict-free ldmatrix (68-word row stride).
#define SAS 136
#define OFF_AHI 0
#define OFF_ALO (64 * SAS)
#define OFF_BHI (2 * 64 * SAS)
#define OFF_BLO (OFF_BHI + 128 * SAS)
#define SM_HALVES (OFF_BLO + 128 * SAS)

__device__ __forceinline__ uint32_t cvta_s(const void* p) {
    uint32_t a;
    asm("{ .reg .u64 t; cvta.to.shared.u64 t, %1; cvt.u32.u64 %0, t; }" : "=r"(a) : "l"(p));
    return a;
}
__device__ __forceinline__ void ldmx4(uint32_t r[4], uint32_t addr) {
    asm volatile("ldmatrix.sync.aligned.m8n8.x4.shared.b16 {%0,%1,%2,%3}, [%4];"
                 : "=r"(r[0]), "=r"(r[1]), "=r"(r[2]), "=r"(r[3]) : "r"(addr));
}
__device__ __forceinline__ void mma16816(float c[4], const uint32_t a[4], const uint32_t b[2]) {
    asm volatile(
        "mma.sync.aligned.m16n8k16.row.col.f32.f16.f16.f32 "
        "{%0,%1,%2,%3},{%4,%5,%6,%7},{%8,%9},{%0,%1,%2,%3};"
        : "+f"(c[0]), "+f"(c[1]), "+f"(c[2]), "+f"(c[3])
        : "r"(a[0]), "r"(a[1]), "r"(a[2]), "r"(a[3]), "r"(b[0]), "r"(b[1]));
}

__global__ void __launch_bounds__(256, 2) k_hmma1(const float* __restrict__ x) {
    extern __shared__ __half sm[];
    uint32_t sbase = cvta_s(sm);
    int tid = threadIdx.x;
    int wid = tid >> 5, lane = tid & 31;
    int wm = wid >> 2, wn = wid & 3;           // 2x4 warp grid, 32x32 each
    int row0 = blockIdx.x * 64;
    int col0 = blockIdx.y * 128;

    // ---- load A: x[row0..+63][0..127] fp32 -> fp16 hi/lo ----
    for (int i = tid; i < 2048; i += 256) {    // 64 rows x 32 float4
        int r = i >> 5, c = (i & 31) * 4;
        int gr = row0 + r;
        float4 v = make_float4(0.f, 0.f, 0.f, 0.f);
        if (gr < NN) v = *(const float4*)(x + (size_t)gr * KIN + c);
        __half h0 = __float2half(v.x), h1 = __float2half(v.y);
        __half h2 = __float2half(v.z), h3 = __float2half(v.w);
        __half l0 = __float2half(v.x - __half2float(h0));
        __half l1 = __float2half(v.y - __half2float(h1));
        __half l2 = __float2half(v.z - __half2float(h2));
        __half l3 = __float2half(v.w - __half2float(h3));
        __half* ah = sm + OFF_AHI + r * SAS + c;
        __half* al = sm + OFF_ALO + r * SAS + c;
        ah[0] = h0; ah[1] = h1; ah[2] = h2; ah[3] = h3;
        al[0] = l0; al[1] = l1; al[2] = l2; al[3] = l3;
    }
    // ---- load B: W^T[col0..+127][0..127] fp16 hi/lo (prepped) ----
    for (int i = tid; i < 2048; i += 256) {    // 128 n x 16 uint4(8 halves)
        int n = i >> 4, k8 = (i & 15) * 8;
        uint4 hv = *(const uint4*)(g_Whi + (size_t)(col0 + n) * KIN + k8);
        uint4 lv = *(const uint4*)(g_Wlo + (size_t)(col0 + n) * KIN + k8);
        *(uint4*)(sm + OFF_BHI + n * SAS + k8) = hv;
        *(uint4*)(sm + OFF_BLO + n * SAS + k8) = lv;
    }
    __syncthreads();

    // ldmatrix per-thread source rows
    int blk = lane >> 3, rowin = lane & 7;
    // A x4: blocks (r0..7,k0),(r8..15,k0),(r0..7,k8),(r8..15,k8)
    int a_r = (blk & 1) * 8 + rowin;
    int a_c = (blk >> 1) * 8;
    // B x4 pair: blocks (n0..7,k0),(n0..7,k8),(n8..15,k0),(n8..15,k8)
    int b_n = (blk >> 1) * 8 + rowin;
    int b_c = (blk & 1) * 8;

    float acc[2][4][4] = {};
#pragma unroll
    for (int ks = 0; ks < 8; ks++) {
        int k0 = ks * 16;
        uint32_t ah[2][4], al[2][4], bh[2][4], bl[2][4];
#pragma unroll
        for (int mt = 0; mt < 2; mt++) {
            int r = wm * 32 + mt * 16 + a_r;
            uint32_t off = (uint32_t)((r * SAS + k0 + a_c) * 2);
            ldmx4(ah[mt], sbase + OFF_AHI * 2 + off);
            ldmx4(al[mt], sbase + OFF_ALO * 2 + off);
        }
#pragma unroll
        for (int pr = 0; pr < 2; pr++) {       // nt pairs (0,1) and (2,3)
            int n = wn * 32 + pr * 16 + b_n;
            uint32_t off = (uint32_t)((n * SAS + k0 + b_c) * 2);
            ldmx4(bh[pr], sbase + OFF_BHI * 2 + off);
            ldmx4(bl[pr], sbase + OFF_BLO * 2 + off);
        }
#pragma unroll
        for (int mt = 0; mt < 2; mt++)
#pragma unroll
            for (int nt = 0; nt < 4; nt++) {
                const uint32_t* bhf = &bh[nt >> 1][(nt & 1) * 2];
                const uint32_t* blf = &bl[nt >> 1][(nt & 1) * 2];
                mma16816(acc[mt][nt], ah[mt], bhf);
                mma16816(acc[mt][nt], al[mt], bhf);
                mma16816(acc[mt][nt], ah[mt], blf);
            }
    }

    // ---- store fp16 h1 ----
#pragma unroll
    for (int mt = 0; mt < 2; mt++) {
        int r = row0 + wm * 32 + mt * 16 + (lane >> 2);
#pragma unroll
        for (int nt = 0; nt < 4; nt++) {
            int gc = col0 + wn * 32 + nt * 8 + (lane & 3) * 2;
            if (r < NN)
                *(__half2*)(g_h1h + (size_t)r * C1 + gc) =
                    __floats2half2_rn(acc[mt][nt][0], acc[mt][nt][1]);
            if (r + 8 < NN)
                *(__half2*)(g_h1h + (size_t)(r + 8) * C1 + gc) =
                    __floats2half2_rn(acc[mt][nt][2], acc[mt][nt][3]);
        }
    }
}

// ---------------- attention logits per (node, head), fp16 h1 -----------------
__global__ void k_asd1(const float* __restrict__ asrc, const float* __restrict__ adst) {
    int tid = blockIdx.x * blockDim.x + threadIdx.x;
    if (tid >= NN * NH) return;
    int n = tid >> 3, h = tid & 7;
    const __half2* hp = (const __half2*)(g_h1h + (size_t)n * C1 + h * HD);
    const float* sa = asrc + h * HD;
    const float* da = adst + h * HD;
    float s = 0.f, d = 0.f;
#pragma unroll
    for (int q = 0; q < 16; q++) {
        float2 f = __half22float2(hp[q]);
        s += f.x * sa[2 * q] + f.y * sa[2 * q + 1];
        d += f.x * da[2 * q] + f.y * da[2 * q + 1];
    }
    g_as1[tid] = s;
    g_ad1[tid] = d;
}

// ---------------- layer-1 aggregation: warp/node, fp16 gather, m=0 softmax ---
__global__ void k_agg1(const float* __restrict__ b1) {
    int warp = (blockIdx.x * blockDim.x + threadIdx.x) >> 5;
    if (warp >= NN) return;
    int lane = threadIdx.x & 31;
    int n = warp;
    int hA = lane >> 3, hB = 4 + (lane >> 3);
    int beg = g_rowptr[n], end = g_rowptr[n + 1];
    float adA = g_ad1[n * NH + hA], adB = g_ad1[n * NH + hB];

    float4 acc0 = make_float4(0.f, 0.f, 0.f, 0.f);
    float4 acc1 = make_float4(0.f, 0.f, 0.f, 0.f);
    float dA = 0.f, dB = 0.f;
    int i = beg;
    for (; i + 1 < end; i += 2) {
        int s0 = g_esrc[i], s1 = g_esrc[i + 1];
        const uint2* p0 = (const uint2*)(g_h1h + (size_t)s0 * C1);
        const uint2* p1 = (const uint2*)(g_h1h + (size_t)s1 * C1);
        float eA0 = lrelu(g_as1[s0 * NH + hA] + adA);
        float eB0 = lrelu(g_as1[s0 * NH + hB] + adB);
        float eA1 = lrelu(g_as1[s1 * NH + hA] + adA);
        float eB1 = lrelu(g_as1[s1 * NH + hB] + adB);
        uint2 ua = p0[lane], ub = p0[32 + lane];
        uint2 va = p1[lane], vb = p1[32 + lane];
        float wA0 = __expf(eA0), wB0 = __expf(eB0);
        float wA1 = __expf(eA1), wB1 = __expf(eB1);
        dA += wA0 + wA1; dB += wB0 + wB1;
        {
            __half2* h = (__half2*)&ua;
            float2 f0 = __half22float2(h[0]), f1 = __half22float2(h[1]);
            acc0.x += wA0 * f0.x; acc0.y += wA0 * f0.y;
            acc0.z += wA0 * f1.x; acc0.w += wA0 * f1.y;
        }
        {
            __half2* h = (__half2*)&ub;
            float2 f0 = __half22float2(h[0]), f1 = __half22float2(h[1]);
            acc1.x += wB0 * f0.x; acc1.y += wB0 * f0.y;
            acc1.z += wB0 * f1.x; acc1.w += wB0 * f1.y;
        }
        {
            __half2* h = (__half2*)&va;
            float2 f0 = __half22float2(h[0]), f1 = __half22float2(h[1]);
            acc0.x += wA1 * f0.x; acc0.y += wA1 * f0.y;
            acc0.z += wA1 * f1.x; acc0.w += wA1 * f1.y;
        }
        {
            __half2* h = (__half2*)&vb;
            float2 f0 = __half22float2(h[0]), f1 = __half22float2(h[1]);
            acc1.x += wB1 * f0.x; acc1.y += wB1 * f0.y;
            acc1.z += wB1 * f1.x; acc1.w += wB1 * f1.y;
        }
    }
    for (; i < end; i++) {
        int s = g_esrc[i];
        const uint2* p = (const uint2*)(g_h1h + (size_t)s * C1);
        float wA = __expf(lrelu(g_as1[s * NH + hA] + adA));
        float wB = __expf(lrelu(g_as1[s * NH + hB] + adB));
        dA += wA; dB += wB;
        uint2 ua = p[lane], ub = p[32 + lane];
        __half2* h0 = (__half2*)&ua;
        __half2* h1 = (__half2*)&ub;
        float2 f0 = __half22float2(h0[0]), f1 = __half22float2(h0[1]);
        float2 f2 = __half22float2(h1[0]), f3 = __half22float2(h1[1]);
        acc0.x += wA * f0.x; acc0.y += wA * f0.y; acc0.z += wA * f1.x; acc0.w += wA * f1.y;
        acc1.x += wB * f2.x; acc1.y += wB * f2.y; acc1.z += wB * f3.x; acc1.w += wB * f3.y;
    }
    float iA = 1.f / dA, iB = 1.f / dB;
    const float4* bp = (const float4*)b1;
    float4 bb0 = bp[lane], bb1 = bp[32 + lane];
    float4 o0, o1;
    o0.x = elu1(acc0.x * iA + bb0.x); o0.y = elu1(acc0.y * iA + bb0.y);
    o0.z = elu1(acc0.z * iA + bb0.z); o0.w = elu1(acc0.w * iA + bb0.w);
    o1.x = elu1(acc1.x * iB + bb1.x); o1.y = elu1(acc1.y * iB + bb1.y);
    o1.z = elu1(acc1.z * iB + bb1.z); o1.w = elu1(acc1.w * iB + bb1.w);
    float4* op = (float4*)(g_h1out + (size_t)n * C1);
    op[lane] = o0;
    op[32 + lane] = o1;
}

// ---------------- fold att2 into W2 ----------------
__global__ void k_w2aug(const float* __restrict__ W2,
                        const float* __restrict__ as2,
                        const float* __restrict__ ad2) {
    int k = blockIdx.x * blockDim.x + threadIdx.x;
    if (k >= C1) return;
    float s = 0.f, d = 0.f;
#pragma unroll
    for (int c = 0; c < NC; c++) {
        float w = W2[k * NC + c];
        g_w2aug[k * 12 + c] = w;
        s += w * as2[c];
        d += w * ad2[c];
    }
    g_w2aug[k * 12 + 10] = s;
    g_w2aug[k * 12 + 11] = d;
}

// ---------------- GEMM2: h2 = h1out @ W2aug ----------------
__global__ void k_gemm2() {
    __shared__ float Ws[C1 * 12];
    for (int i = threadIdx.x; i < C1 * 12; i += blockDim.x) Ws[i] = g_w2aug[i];
    __syncthreads();
    int n = blockIdx.x * blockDim.x + threadIdx.x;
    if (n >= NN) return;
    float acc[12];
#pragma unroll
    for (int c = 0; c < 12; c++) acc[c] = 0.f;
    const float4* xp = (const float4*)(g_h1out + (size_t)n * C1);
    for (int q = 0; q < 64; q++) {
        float4 x = xp[q];
        const float* w = &Ws[(q * 4) * 12];
#pragma unroll
        for (int c = 0; c < 12; c++)
            acc[c] += x.x * w[c] + x.y * w[12 + c] + x.z * w[24 + c] + x.w * w[36 + c];
    }
#pragma unroll
    for (int c = 0; c < 12; c++) g_h2[n * 12 + c] = acc[c];
}

// ---------------- layer-2 agg + log-softmax ----------------
__global__ void k_agg2(const float* __restrict__ b2, float* __restrict__ out) {
    int warp = (blockIdx.x * blockDim.x + threadIdx.x) >> 5;
    if (warp >= NN) return;
    int lane = threadIdx.x & 31;
    int n = warp;
    float ad2v = g_h2[n * 12 + 11];
    int beg = g_rowptr[n], end = g_rowptr[n + 1];

    float4 A = make_float4(0.f, 0.f, 0.f, 0.f);
    float4 Bv = make_float4(0.f, 0.f, 0.f, 0.f);
    float c8 = 0.f, c9 = 0.f, den = 0.f;
    for (int i = beg + lane; i < end; i += 32) {
        int s = g_esrc[i];
        const float4* hp = (const float4*)(g_h2 + (size_t)s * 12);
        float4 r0 = hp[0], r1 = hp[1], r2 = hp[2];
        float w = __expf(lrelu(r2.z + ad2v));
        den += w;
        A.x += w * r0.x; A.y += w * r0.y; A.z += w * r0.z; A.w += w * r0.w;
        Bv.x += w * r1.x; Bv.y += w * r1.y; Bv.z += w * r1.z; Bv.w += w * r1.w;
        c8 += w * r2.x; c9 += w * r2.y;
    }
#pragma unroll
    for (int o = 16; o > 0; o >>= 1) {
        A.x += __shfl_xor_sync(0xffffffffu, A.x, o);
        A.y += __shfl_xor_sync(0xffffffffu, A.y, o);
        A.z += __shfl_xor_sync(0xffffffffu, A.z, o);
        A.w += __shfl_xor_sync(0xffffffffu, A.w, o);
        Bv.x += __shfl_xor_sync(0xffffffffu, Bv.x, o);
        Bv.y += __shfl_xor_sync(0xffffffffu, Bv.y, o);
        Bv.z += __shfl_xor_sync(0xffffffffu, Bv.z, o);
        Bv.w += __shfl_xor_sync(0xffffffffu, Bv.w, o);
        c8  += __shfl_xor_sync(0xffffffffu, c8, o);
        c9  += __shfl_xor_sync(0xffffffffu, c9, o);
        den += __shfl_xor_sync(0xffffffffu, den, o);
    }
    if (lane == 0) {
        float inv = 1.f / den;
        float v[NC];
        v[0] = A.x * inv + b2[0]; v[1] = A.y * inv + b2[1];
        v[2] = A.z * inv + b2[2]; v[3] = A.w * inv + b2[3];
        v[4] = Bv.x * inv + b2[4]; v[5] = Bv.y * inv + b2[5];
        v[6] = Bv.z * inv + b2[6]; v[7] = Bv.w * inv + b2[7];
        v[8] = c8 * inv + b2[8];  v[9] = c9 * inv + b2[9];
        float mx = v[0];
#pragma unroll
        for (int c = 1; c < NC; c++) mx = fmaxf(mx, v[c]);
        float sm = 0.f;
#pragma unroll
        for (int c = 0; c < NC; c++) sm += __expf(v[c] - mx);
        float l = mx + __logf(sm);
#pragma unroll
        for (int c = 0; c < NC; c++) out[(size_t)n * NC + c] = v[c] - l;
    }
}

// ---------------- launch ----------------
extern "C" void kernel_launch(void* const* d_in, const int* in_sizes, int n_in,
                              void* d_out, int out_size) {
    const float* x   = (const float*)d_in[0];
    const void*  ei  = d_in[1];
    const float* W1  = (const float*)d_in[2];
    const float* as1 = (const float*)d_in[3];
    const float* ad1 = (const float*)d_in[4];
    const float* b1  = (const float*)d_in[5];
    const float* W2  = (const float*)d_in[6];
    const float* as2 = (const float*)d_in[7];
    const float* ad2 = (const float*)d_in[8];
    const float* b2  = (const float*)d_in[9];
    float* out = (float*)d_out;

    int smem_bytes = SM_HALVES * (int)sizeof(__half);   // ~102 KB
    cudaFuncSetAttribute(k_hmma1, cudaFuncAttributeMaxDynamicSharedMemorySize, smem_bytes);

    k_init<<<(NN + 255) / 256, 256>>>(ei);                  // 1
    k_hist<<<(EP + 255) / 256, 256>>>(ei);                  // 2
    k_prepB<<<(KIN * C1 + 255) / 256, 256>>>(W1);           // 3
    dim3 gg((NN + 63) / 64, 2);
    k_hmma1<<<gg, 256, smem_bytes>>>(x);                    // 4 <- ncu slot
    k_scan1<<<196, 256>>>();                                // 5
    k_scan2<<<1, 256>>>();                                  // 6
    k_scan3<<<196, 256>>>();                                // 7
    k_scatter<<<(EP + 255) / 256, 256>>>(ei);               // 8
    k_asd1<<<(NN * NH + 255) / 256, 256>>>(as1, ad1);       // 9
    k_agg1<<<(NN + 7) / 8, 256>>>(b1);                      // 10
    k_w2aug<<<1, 256>>>(W2, as2, ad2);                      // 11
    k_gemm2<<<(NN + 127) / 128, 128>>>();                   // 12
    k_agg2<<<(NN + 7) / 8, 256>>>(b2, out);                 // 13
}

// round 8
// speedup vs baseline: 1.5021x; 1.1280x over previous
#include <cuda_runtime.h>
#include <cuda_fp16.h>
#include <math.h>
#include <stdint.h>

// ---------------- problem constants ----------------
#define NN   50000
#define EE   800000
#define EP   (EE + NN)
#define KIN  128
#define C1   256              // 8 heads * 32
#define NH   8
#define HD   32
#define NC   10
#define NEG  0.2f
#define NCTA 148              // SM count (one persistent wave x 2 CTAs/SM)

// ---------------- scratch globals ----------------
__device__ __align__(256) __half g_h1h[(size_t)NN * C1];       // x@W1 in fp16
__device__ __align__(256) float  g_h1out[(size_t)NN * C1];     // layer-1 out
__device__ __align__(256) float2 g_asp[NN * 4];                // (as[h], as[h+4])
__device__ __align__(256) float2 g_adp[NN * 4];                // (ad[h], ad[h+4])
__device__ __align__(256) float  g_h2[NN * 12];
__device__ __align__(256) float  g_w2aug[C1 * 12];
__device__ __align__(256) __half g_Whi[C1 * KIN];              // W1^T hi  [n][k]
__device__ __align__(256) __half g_Wlo[C1 * KIN];              // W1^T lo  [n][k]
__device__ __align__(256) int    g_rowptr[NN + 1];
__device__ __align__(256) int    g_cursor[NN];
__device__ __align__(256) int    g_counts[NN];
__device__ __align__(256) int    g_esrc[EP];
__device__ __align__(256) int    g_bsums[256];
__device__ int g_is64;

// ---------------- small helpers ----------------
__device__ __forceinline__ int eidx(const void* p, long long i, int is64) {
    return is64 ? (int)((const long long*)p)[i] : ((const int*)p)[i];
}
__device__ __forceinline__ float lrelu(float x) { return x > 0.f ? x : NEG * x; }
__device__ __forceinline__ float elu1(float x)  { return x > 0.f ? x : (__expf(x) - 1.f); }

// ---------------- init: zero counts + dtype sniff ----------------------------
__global__ void k_init(const void* ei) {
    int i = blockIdx.x * blockDim.x + threadIdx.x;
    if (i < NN) g_counts[i] = 0;
    if (i == 0) {
        const long long* p = (const long long*)ei;
        int ok = 1;
        for (int q = 0; q < 64; q++) {
            long long v = p[q];
            if (v < 0 || v >= NN) ok = 0;
        }
        g_is64 = ok;
    }
}

// ---------------- CSR build ----------------
__global__ void k_hist(const void* ei) {
    int i = blockIdx.x * blockDim.x + threadIdx.x;
    if (i >= EP) return;
    int is64 = g_is64;
    int d = (i < EE) ? eidx(ei, (long long)EE + i, is64) : (i - EE);
    atomicAdd(&g_counts[d], 1);
}

__global__ void k_scan1() {
    __shared__ int s[256];
    int t = threadIdx.x;
    int i = blockIdx.x * 256 + t;
    s[t] = (i < NN) ? g_counts[i] : 0;
    __syncthreads();
    for (int o = 128; o > 0; o >>= 1) {
        if (t < o) s[t] += s[t + o];
        __syncthreads();
    }
    if (t == 0) g_bsums[blockIdx.x] = s[0];
}

__global__ void k_scan2() {
    __shared__ int s[256];
    int t = threadIdx.x;
    int v = (t < 196) ? g_bsums[t] : 0;
    s[t] = v;
    __syncthreads();
    for (int o = 1; o < 256; o <<= 1) {
        int x = (t >= o) ? s[t - o] : 0;
        __syncthreads();
        s[t] += x;
        __syncthreads();
    }
    g_bsums[t] = s[t] - v;
}

__global__ void k_scan3() {
    __shared__ int s[256];
    int t = threadIdx.x;
    int i = blockIdx.x * 256 + t;
    int v = (i < NN) ? g_counts[i] : 0;
    s[t] = v;
    __syncthreads();
    for (int o = 1; o < 256; o <<= 1) {
        int x = (t >= o) ? s[t - o] : 0;
        __syncthreads();
        s[t] += x;
        __syncthreads();
    }
    int excl = s[t] - v + g_bsums[blockIdx.x];
    if (i < NN) { g_rowptr[i] = excl; g_cursor[i] = excl; }
    if (i == 0) g_rowptr[NN] = EP;
}

__global__ void k_scatter(const void* ei) {
    int i = blockIdx.x * blockDim.x + threadIdx.x;
    if (i >= EP) return;
    int is64 = g_is64;
    int s, d;
    if (i < EE) {
        s = eidx(ei, i, is64);
        d = eidx(ei, (long long)EE + i, is64);
    } else {
        s = d = i - EE;
    }
    int pos = atomicAdd(&g_cursor[d], 1);
    g_esrc[pos] = s;
}

// ---------------- prep: W1 -> transposed fp16 hi/lo splits --------------------
__global__ void k_prepB(const float* __restrict__ W1) {
    int i = blockIdx.x * blockDim.x + threadIdx.x;
    if (i >= KIN * C1) return;
    int k = i >> 8, n = i & 255;
    float v = W1[i];                       // W1[k][n] row-major
    __half hi = __float2half(v);
    __half lo = __float2half(v - __half2float(hi));
    g_Whi[n * KIN + k] = hi;
    g_Wlo[n * KIN + k] = lo;
}

// ---------------- GEMM1: persistent CTAs, mma.sync hi/lo, pipelined A --------
// Grid (148, 2). CTA owns a 128-col half of W (SMEM, loaded once) and walks
// M-tiles of 32 rows with double-buffered A (gmem loads overlap compute).
#define SAS 136
#define OFF_BHI 0
#define OFF_BLO (128 * SAS)
#define OFF_A   (256 * SAS)
#define ABUF(b) (OFF_A + (b) * (64 * SAS))      // per buf: hi 32xSAS, lo 32xSAS
#define SM_HALVES (OFF_A + 2 * 64 * SAS)        // 384*SAS halves (~102 KB)

__device__ __forceinline__ uint32_t cvta_s(const void* p) {
    uint32_t a;
    asm("{ .reg .u64 t; cvta.to.shared.u64 t, %1; cvt.u32.u64 %0, t; }" : "=r"(a) : "l"(p));
    return a;
}
__device__ __forceinline__ void ldmx4(uint32_t r[4], uint32_t addr) {
    asm volatile("ldmatrix.sync.aligned.m8n8.x4.shared.b16 {%0,%1,%2,%3}, [%4];"
                 : "=r"(r[0]), "=r"(r[1]), "=r"(r[2]), "=r"(r[3]) : "r"(addr));
}
__device__ __forceinline__ void mma16816(float c[4], const uint32_t a[4], const uint32_t b[2]) {
    asm volatile(
        "mma.sync.aligned.m16n8k16.row.col.f32.f16.f16.f32 "
        "{%0,%1,%2,%3},{%4,%5,%6,%7},{%8,%9},{%0,%1,%2,%3};"
        : "+f"(c[0]), "+f"(c[1]), "+f"(c[2]), "+f"(c[3])
        : "r"(a[0]), "r"(a[1]), "r"(a[2]), "r"(a[3]), "r"(b[0]), "r"(b[1]));
}
__device__ __forceinline__ void load_a_regs(float4 v[4], const float* __restrict__ x,
                                            int t, int ar, int ac) {
    int gr = t * 32 + ar;
    if (gr < NN) {
        const float4* p = (const float4*)(x + (size_t)gr * KIN + ac);
        v[0] = p[0]; v[1] = p[1]; v[2] = p[2]; v[3] = p[3];
    } else {
        v[0] = v[1] = v[2] = v[3] = make_float4(0.f, 0.f, 0.f, 0.f);
    }
}
__device__ __forceinline__ void cvt_store_a(__half* sm, int buf, const float4 v[4],
                                            int ar, int ac) {
    __half* ah = sm + ABUF(buf) + ar * SAS + ac;
    __half* al = ah + 32 * SAS;
#pragma unroll
    for (int j = 0; j < 4; j++) {
        float4 f = v[j];
        __half h0 = __float2half(f.x), h1 = __float2half(f.y);
        __half h2 = __float2half(f.z), h3 = __float2half(f.w);
        ah[j * 4 + 0] = h0; ah[j * 4 + 1] = h1; ah[j * 4 + 2] = h2; ah[j * 4 + 3] = h3;
        al[j * 4 + 0] = __float2half(f.x - __half2float(h0));
        al[j * 4 + 1] = __float2half(f.y - __half2float(h1));
        al[j * 4 + 2] = __float2half(f.z - __half2float(h2));
        al[j * 4 + 3] = __float2half(f.w - __half2float(h3));
    }
}

__global__ void __launch_bounds__(256, 2) k_hmma1(const float* __restrict__ x) {
    extern __shared__ __half sm[];
    uint32_t sbase = cvta_s(sm);
    int tid = threadIdx.x;
    int wid = tid >> 5, lane = tid & 31;
    int wm = wid >> 2, wn = wid & 3;           // 2x4 warp grid: 16 rows x 32 cols
    int col0 = blockIdx.y * 128;
    int cx = blockIdx.x;

    // ---- load B half (once): 128 n x 128 k, hi/lo ----
    for (int i = tid; i < 2048; i += 256) {
        int n = i >> 4, k8 = (i & 15) * 8;
        uint4 hv = *(const uint4*)(g_Whi + (size_t)(col0 + n) * KIN + k8);
        uint4 lv = *(const uint4*)(g_Wlo + (size_t)(col0 + n) * KIN + k8);
        *(uint4*)(sm + OFF_BHI + n * SAS + k8) = hv;
        *(uint4*)(sm + OFF_BLO + n * SAS + k8) = lv;
    }

    int ar = tid >> 3;                 // A slice: row 0..31
    int ac = (tid & 7) * 16;           // 16 consecutive floats
    int blk = lane >> 3, rowin = lane & 7;
    int a_r = (blk & 1) * 8 + rowin, a_c = (blk >> 1) * 8;
    int b_n = (blk >> 1) * 8 + rowin, b_c = (blk & 1) * 8;
    const int T = (NN + 31) / 32;      // 1563

    int t = cx;
    {
        float4 v0[4];
        load_a_regs(v0, x, t, ar, ac);
        cvt_store_a(sm, 0, v0, ar, ac);
    }
    __syncthreads();

    int cur = 0;
    for (; t < T; t += NCTA) {
        int tn = t + NCTA;
        bool have_next = (tn < T);
        float4 vnext[4];
        if (have_next) load_a_regs(vnext, x, tn, ar, ac);   // LDGs in flight

        float acc[4][4] = {};
#pragma unroll
        for (int ks = 0; ks < 8; ks++) {
            int k0 = ks * 16;
            uint32_t ah4[4], al4[4], bh[2][4], bl[2][4];
            uint32_t aoff = (uint32_t)((ABUF(cur) + (wm * 16 + a_r) * SAS + k0 + a_c) * 2);
            ldmx4(ah4, sbase + aoff);
            ldmx4(al4, sbase + aoff + 32 * SAS * 2);
#pragma unroll
            for (int pr = 0; pr < 2; pr++) {
                int nB = wn * 32 + pr * 16 + b_n;
                uint32_t boff = (uint32_t)((OFF_BHI + nB * SAS + k0 + b_c) * 2);
                ldmx4(bh[pr], sbase + boff);
                ldmx4(bl[pr], sbase + boff + OFF_BLO * 2);
            }
#pragma unroll
            for (int nt = 0; nt < 4; nt++)
                mma16816(acc[nt], ah4, &bh[nt >> 1][(nt & 1) * 2]);
#pragma unroll
            for (int nt = 0; nt < 4; nt++)
                mma16816(acc[nt], al4, &bh[nt >> 1][(nt & 1) * 2]);
#pragma unroll
            for (int nt = 0; nt < 4; nt++)
                mma16816(acc[nt], ah4, &bl[nt >> 1][(nt & 1) * 2]);
        }

        // ---- epilogue: store fp16 h1 for tile t ----
        int r = t * 32 + wm * 16 + (lane >> 2);
#pragma unroll
        for (int nt = 0; nt < 4; nt++) {
            int gc = col0 + wn * 32 + nt * 8 + (lane & 3) * 2;
            if (r < NN)
                *(__half2*)(g_h1h + (size_t)r * C1 + gc) =
                    __floats2half2_rn(acc[nt][0], acc[nt][1]);
            if (r + 8 < NN)
                *(__half2*)(g_h1h + (size_t)(r + 8) * C1 + gc) =
                    __floats2half2_rn(acc[nt][2], acc[nt][3]);
        }

        if (have_next) cvt_store_a(sm, cur ^ 1, vnext, ar, ac);
        __syncthreads();
        cur ^= 1;
    }
}

// ---------------- attention logits: thread per (node, h4), packed pairs ------
__global__ void k_asd1(const float* __restrict__ asrc, const float* __restrict__ adst) {
    int tid = blockIdx.x * blockDim.x + threadIdx.x;
    if (tid >= NN * 4) return;
    int n = tid >> 2, h4 = tid & 3;
    const __half2* hpA = (const __half2*)(g_h1h + (size_t)n * C1 + h4 * HD);
    const __half2* hpB = (const __half2*)(g_h1h + (size_t)n * C1 + (h4 + 4) * HD);
    const float* saA = asrc + h4 * HD;        const float* daA = adst + h4 * HD;
    const float* saB = asrc + (h4 + 4) * HD;  const float* daB = adst + (h4 + 4) * HD;
    float sA = 0.f, dA = 0.f, sB = 0.f, dB = 0.f;
#pragma unroll
    for (int q = 0; q < 16; q++) {
        float2 fA = __half22float2(hpA[q]);
        float2 fB = __half22float2(hpB[q]);
        sA += fA.x * saA[2 * q] + fA.y * saA[2 * q + 1];
        dA += fA.x * daA[2 * q] + fA.y * daA[2 * q + 1];
        sB += fB.x * saB[2 * q] + fB.y * saB[2 * q + 1];
        dB += fB.x * daB[2 * q] + fB.y * daB[2 * q + 1];
    }
    g_asp[tid] = make_float2(sA, sB);
    g_adp[tid] = make_float2(dA, dB);
}

// ---------------- layer-1 aggregation: warp/node, fp16 gather, unroll 4 ------
__device__ __forceinline__ void agg_edge(float2 sp, float2 adp, uint2 ua, uint2 ub,
                                         float4& acc0, float4& acc1,
                                         float& dA, float& dB) {
    float wA = __expf(lrelu(sp.x + adp.x));
    float wB = __expf(lrelu(sp.y + adp.y));
    dA += wA; dB += wB;
    __half2* h0 = (__half2*)&ua;
    __half2* h1 = (__half2*)&ub;
    float2 f0 = __half22float2(h0[0]), f1 = __half22float2(h0[1]);
    float2 f2 = __half22float2(h1[0]), f3 = __half22float2(h1[1]);
    acc0.x += wA * f0.x; acc0.y += wA * f0.y; acc0.z += wA * f1.x; acc0.w += wA * f1.y;
    acc1.x += wB * f2.x; acc1.y += wB * f2.y; acc1.z += wB * f3.x; acc1.w += wB * f3.y;
}

__global__ void k_agg1(const float* __restrict__ b1) {
    int warp = (blockIdx.x * blockDim.x + threadIdx.x) >> 5;
    if (warp >= NN) return;
    int lane = threadIdx.x & 31;
    int n = warp;
    int h4 = lane >> 3;
    int beg = g_rowptr[n], end = g_rowptr[n + 1];
    float2 adp = g_adp[n * 4 + h4];

    float4 acc0 = make_float4(0.f, 0.f, 0.f, 0.f);
    float4 acc1 = make_float4(0.f, 0.f, 0.f, 0.f);
    float dA = 0.f, dB = 0.f;
    int i = beg;
    for (; i + 3 < end; i += 4) {
        int s0 = g_esrc[i], s1 = g_esrc[i + 1], s2 = g_esrc[i + 2], s3 = g_esrc[i + 3];
        float2 p0 = g_asp[s0 * 4 + h4], p1 = g_asp[s1 * 4 + h4];
        float2 p2 = g_asp[s2 * 4 + h4], p3 = g_asp[s3 * 4 + h4];
        const uint2* q0 = (const uint2*)(g_h1h + (size_t)s0 * C1);
        const uint2* q1 = (const uint2*)(g_h1h + (size_t)s1 * C1);
        const uint2* q2 = (const uint2*)(g_h1h + (size_t)s2 * C1);
        const uint2* q3 = (const uint2*)(g_h1h + (size_t)s3 * C1);
        uint2 u0a = q0[lane], u0b = q0[32 + lane];
        uint2 u1a = q1[lane], u1b = q1[32 + lane];
        uint2 u2a = q2[lane], u2b = q2[32 + lane];
        uint2 u3a = q3[lane], u3b = q3[32 + lane];
        agg_edge(p0, adp, u0a, u0b, acc0, acc1, dA, dB);
        agg_edge(p1, adp, u1a, u1b, acc0, acc1, dA, dB);
        agg_edge(p2, adp, u2a, u2b, acc0, acc1, dA, dB);
        agg_edge(p3, adp, u3a, u3b, acc0, acc1, dA, dB);
    }
    for (; i < end; i++) {
        int s = g_esrc[i];
        float2 p = g_asp[s * 4 + h4];
        const uint2* q = (const uint2*)(g_h1h + (size_t)s * C1);
        uint2 ua = q[lane], ub = q[32 + lane];
        agg_edge(p, adp, ua, ub, acc0, acc1, dA, dB);
    }
    float iA = 1.f / dA, iB = 1.f / dB;
    const float4* bp = (const float4*)b1;
    float4 bb0 = bp[lane], bb1 = bp[32 + lane];
    float4 o0, o1;
    o0.x = elu1(acc0.x * iA + bb0.x); o0.y = elu1(acc0.y * iA + bb0.y);
    o0.z = elu1(acc0.z * iA + bb0.z); o0.w = elu1(acc0.w * iA + bb0.w);
    o1.x = elu1(acc1.x * iB + bb1.x); o1.y = elu1(acc1.y * iB + bb1.y);
    o1.z = elu1(acc1.z * iB + bb1.z); o1.w = elu1(acc1.w * iB + bb1.w);
    float4* op = (float4*)(g_h1out + (size_t)n * C1);
    op[lane] = o0;
    op[32 + lane] = o1;
}

// ---------------- fold att2 into W2 ----------------
__global__ void k_w2aug(const float* __restrict__ W2,
                        const float* __restrict__ as2,
                        const float* __restrict__ ad2) {
    int k = blockIdx.x * blockDim.x + threadIdx.x;
    if (k >= C1) return;
    float s = 0.f, d = 0.f;
#pragma unroll
    for (int c = 0; c < NC; c++) {
        float w = W2[k * NC + c];
        g_w2aug[k * 12 + c] = w;
        s += w * as2[c];
        d += w * ad2[c];
    }
    g_w2aug[k * 12 + 10] = s;
    g_w2aug[k * 12 + 11] = d;
}

// ---------------- GEMM2: h2 = h1out @ W2aug ----------------
__global__ void k_gemm2() {
    __shared__ float Ws[C1 * 12];
    for (int i = threadIdx.x; i < C1 * 12; i += blockDim.x) Ws[i] = g_w2aug[i];
    __syncthreads();
    int n = blockIdx.x * blockDim.x + threadIdx.x;
    if (n >= NN) return;
    float acc[12];
#pragma unroll
    for (int c = 0; c < 12; c++) acc[c] = 0.f;
    const float4* xp = (const float4*)(g_h1out + (size_t)n * C1);
    for (int q = 0; q < 64; q++) {
        float4 x = xp[q];
        const float* w = &Ws[(q * 4) * 12];
#pragma unroll
        for (int c = 0; c < 12; c++)
            acc[c] += x.x * w[c] + x.y * w[12 + c] + x.z * w[24 + c] + x.w * w[36 + c];
    }
#pragma unroll
    for (int c = 0; c < 12; c++) g_h2[n * 12 + c] = acc[c];
}

// ---------------- layer-2 agg + log-softmax ----------------
__global__ void k_agg2(const float* __restrict__ b2, float* __restrict__ out) {
    int warp = (blockIdx.x * blockDim.x + threadIdx.x) >> 5;
    if (warp >= NN) return;
    int lane = threadIdx.x & 31;
    int n = warp;
    float ad2v = g_h2[n * 12 + 11];
    int beg = g_rowptr[n], end = g_rowptr[n + 1];

    float4 A = make_float4(0.f, 0.f, 0.f, 0.f);
    float4 Bv = make_float4(0.f, 0.f, 0.f, 0.f);
    float c8 = 0.f, c9 = 0.f, den = 0.f;
    for (int i = beg + lane; i < end; i += 32) {
        int s = g_esrc[i];
        const float4* hp = (const float4*)(g_h2 + (size_t)s * 12);
        float4 r0 = hp[0], r1 = hp[1], r2 = hp[2];
        float w = __expf(lrelu(r2.z + ad2v));
        den += w;
        A.x += w * r0.x; A.y += w * r0.y; A.z += w * r0.z; A.w += w * r0.w;
        Bv.x += w * r1.x; Bv.y += w * r1.y; Bv.z += w * r1.z; Bv.w += w * r1.w;
        c8 += w * r2.x; c9 += w * r2.y;
    }
#pragma unroll
    for (int o = 16; o > 0; o >>= 1) {
        A.x += __shfl_xor_sync(0xffffffffu, A.x, o);
        A.y += __shfl_xor_sync(0xffffffffu, A.y, o);
        A.z += __shfl_xor_sync(0xffffffffu, A.z, o);
        A.w += __shfl_xor_sync(0xffffffffu, A.w, o);
        Bv.x += __shfl_xor_sync(0xffffffffu, Bv.x, o);
        Bv.y += __shfl_xor_sync(0xffffffffu, Bv.y, o);
        Bv.z += __shfl_xor_sync(0xffffffffu, Bv.z, o);
        Bv.w += __shfl_xor_sync(0xffffffffu, Bv.w, o);
        c8  += __shfl_xor_sync(0xffffffffu, c8, o);
        c9  += __shfl_xor_sync(0xffffffffu, c9, o);
        den += __shfl_xor_sync(0xffffffffu, den, o);
    }
    if (lane == 0) {
        float inv = 1.f / den;
        float v[NC];
        v[0] = A.x * inv + b2[0]; v[1] = A.y * inv + b2[1];
        v[2] = A.z * inv + b2[2]; v[3] = A.w * inv + b2[3];
        v[4] = Bv.x * inv + b2[4]; v[5] = Bv.y * inv + b2[5];
        v[6] = Bv.z * inv + b2[6]; v[7] = Bv.w * inv + b2[7];
        v[8] = c8 * inv + b2[8];  v[9] = c9 * inv + b2[9];
        float mx = v[0];
#pragma unroll
        for (int c = 1; c < NC; c++) mx = fmaxf(mx, v[c]);
        float sm = 0.f;
#pragma unroll
        for (int c = 0; c < NC; c++) sm += __expf(v[c] - mx);
        float l = mx + __logf(sm);
#pragma unroll
        for (int c = 0; c < NC; c++) out[(size_t)n * NC + c] = v[c] - l;
    }
}

// ---------------- launch ----------------
extern "C" void kernel_launch(void* const* d_in, const int* in_sizes, int n_in,
                              void* d_out, int out_size) {
    const float* x   = (const float*)d_in[0];
    const void*  ei  = d_in[1];
    const float* W1  = (const float*)d_in[2];
    const float* as1 = (const float*)d_in[3];
    const float* ad1 = (const float*)d_in[4];
    const float* b1  = (const float*)d_in[5];
    const float* W2  = (const float*)d_in[6];
    const float* as2 = (const float*)d_in[7];
    const float* ad2 = (const float*)d_in[8];
    const float* b2  = (const float*)d_in[9];
    float* out = (float*)d_out;

    int smem_bytes = SM_HALVES * (int)sizeof(__half);   // ~102 KB
    cudaFuncSetAttribute(k_hmma1, cudaFuncAttributeMaxDynamicSharedMemorySize, smem_bytes);

    k_init<<<(NN + 255) / 256, 256>>>(ei);                  // 1
    k_hist<<<(EP + 255) / 256, 256>>>(ei);                  // 2
    k_prepB<<<(KIN * C1 + 255) / 256, 256>>>(W1);           // 3
    dim3 gg(NCTA, 2);
    k_hmma1<<<gg, 256, smem_bytes>>>(x);                    // 4 <- ncu slot
    k_scan1<<<196, 256>>>();                                // 5
    k_scan2<<<1, 256>>>();                                  // 6
    k_scan3<<<196, 256>>>();                                // 7
    k_scatter<<<(EP + 255) / 256, 256>>>(ei);               // 8
    k_asd1<<<(NN * 4 + 255) / 256, 256>>>(as1, ad1);        // 9
    k_agg1<<<(NN + 7) / 8, 256>>>(b1);                      // 10
    k_w2aug<<<1, 256>>>(W2, as2, ad2);                      // 11
    k_gemm2<<<(NN + 127) / 128, 128>>>();                   // 12
    k_agg2<<<(NN + 7) / 8, 256>>>(b2, out);                 // 13
}

// round 9
// speedup vs baseline: 1.5925x; 1.0602x over previous
#include <cuda_runtime.h>
#include <cuda_fp16.h>
#include <math.h>
#include <stdint.h>

// ---------------- problem constants ----------------
#define NN   50000
#define EE   800000
#define EP   (EE + NN)
#define KIN  128
#define C1   256              // 8 heads * 32
#define NH   8
#define HD   32
#define NC   10
#define NEG  0.2f
#define NCTA 148

// ---------------- scratch globals ----------------
__device__ __align__(256) __half g_h1h[(size_t)NN * C1];       // x@W1 in fp16
__device__ __align__(256) float  g_h1out[(size_t)NN * C1];     // layer-1 out
__device__ __align__(256) float  g_as1[NN * NH];
__device__ __align__(256) float  g_ad1[NN * NH];
__device__ __align__(256) float  g_h2[NN * 12];
__device__ __align__(256) __half g_Whi[C1 * KIN];              // W1^T hi  [n][k]
__device__ __align__(256) __half g_Wlo[C1 * KIN];              // W1^T lo  [n][k]
__device__ __align__(256) int    g_rowptr[NN + 1];
__device__ __align__(256) int    g_cursor[NN];
__device__ __align__(256) int    g_counts[NN];
__device__ __align__(256) int    g_esrc[EP];
__device__ __align__(256) int    g_bsums[256];
__device__ int g_is64;

// ---------------- small helpers ----------------
__device__ __forceinline__ int eidx(const void* p, long long i, int is64) {
    return is64 ? (int)((const long long*)p)[i] : ((const int*)p)[i];
}
__device__ __forceinline__ float lrelu(float x) { return x > 0.f ? x : NEG * x; }
__device__ __forceinline__ float elu1(float x)  { return x > 0.f ? x : (__expf(x) - 1.f); }

// ---------------- init: zero counts + dtype sniff + W1 hi/lo prep ------------
__global__ void k_initprep(const void* ei, const float* __restrict__ W1) {
    int i = blockIdx.x * blockDim.x + threadIdx.x;
    if (i < NN) g_counts[i] = 0;
    if (i < KIN * C1) {
        int k = i >> 8, n = i & 255;
        float v = W1[i];                   // W1[k][n] row-major
        __half hi = __float2half(v);
        __half lo = __float2half(v - __half2float(hi));
        g_Whi[n * KIN + k] = hi;
        g_Wlo[n * KIN + k] = lo;
    }
    if (i == 0) {
        const long long* p = (const long long*)ei;
        int ok = 1;
        for (int q = 0; q < 64; q++) {
            long long v = p[q];
            if (v < 0 || v >= NN) ok = 0;
        }
        g_is64 = ok;
    }
}

// ---------------- CSR build ----------------
__global__ void k_hist(const void* ei) {
    int i = blockIdx.x * blockDim.x + threadIdx.x;
    if (i >= EP) return;
    int is64 = g_is64;
    int d = (i < EE) ? eidx(ei, (long long)EE + i, is64) : (i - EE);
    atomicAdd(&g_counts[d], 1);
}

__global__ void k_scan1() {
    __shared__ int s[256];
    int t = threadIdx.x;
    int i = blockIdx.x * 256 + t;
    s[t] = (i < NN) ? g_counts[i] : 0;
    __syncthreads();
    for (int o = 128; o > 0; o >>= 1) {
        if (t < o) s[t] += s[t + o];
        __syncthreads();
    }
    if (t == 0) g_bsums[blockIdx.x] = s[0];
}

__global__ void k_scan2() {
    __shared__ int s[256];
    int t = threadIdx.x;
    int v = (t < 196) ? g_bsums[t] : 0;
    s[t] = v;
    __syncthreads();
    for (int o = 1; o < 256; o <<= 1) {
        int x = (t >= o) ? s[t - o] : 0;
        __syncthreads();
        s[t] += x;
        __syncthreads();
    }
    g_bsums[t] = s[t] - v;
}

__global__ void k_scan3() {
    __shared__ int s[256];
    int t = threadIdx.x;
    int i = blockIdx.x * 256 + t;
    int v = (i < NN) ? g_counts[i] : 0;
    s[t] = v;
    __syncthreads();
    for (int o = 1; o < 256; o <<= 1) {
        int x = (t >= o) ? s[t - o] : 0;
        __syncthreads();
        s[t] += x;
        __syncthreads();
    }
    int excl = s[t] - v + g_bsums[blockIdx.x];
    if (i < NN) { g_rowptr[i] = excl; g_cursor[i] = excl; }
    if (i == 0) g_rowptr[NN] = EP;
}

__global__ void k_scatter(const void* ei) {
    int i = blockIdx.x * blockDim.x + threadIdx.x;
    if (i >= EP) return;
    int is64 = g_is64;
    int s, d;
    if (i < EE) {
        s = eidx(ei, i, is64);
        d = eidx(ei, (long long)EE + i, is64);
    } else {
        s = d = i - EE;
    }
    int pos = atomicAdd(&g_cursor[d], 1);
    g_esrc[pos] = s;
}

// ---------------- GEMM1 + attn-logits: persistent, mma.sync hi/lo ------------
// Grid (148, 2). CTA owns a 128-col half of W (SMEM, once); walks 32-row
// M-tiles with double-buffered A. Warp wn owns head h = 4*blockIdx.y + wn and
// computes a_s/a_d from fp32 accumulators (fused asd).
#define SAS 136
#define OFF_BHI 0
#define OFF_BLO (128 * SAS)
#define OFF_A   (256 * SAS)
#define ABUF(b) (OFF_A + (b) * (64 * SAS))      // per buf: hi 32xSAS, lo 32xSAS
#define SM_HALVES (OFF_A + 2 * 64 * SAS)        // ~102 KB

__device__ __forceinline__ uint32_t cvta_s(const void* p) {
    uint32_t a;
    asm("{ .reg .u64 t; cvta.to.shared.u64 t, %1; cvt.u32.u64 %0, t; }" : "=r"(a) : "l"(p));
    return a;
}
__device__ __forceinline__ void ldmx4(uint32_t r[4], uint32_t addr) {
    asm volatile("ldmatrix.sync.aligned.m8n8.x4.shared.b16 {%0,%1,%2,%3}, [%4];"
                 : "=r"(r[0]), "=r"(r[1]), "=r"(r[2]), "=r"(r[3]) : "r"(addr));
}
__device__ __forceinline__ void mma16816(float c[4], const uint32_t a[4], const uint32_t b[2]) {
    asm volatile(
        "mma.sync.aligned.m16n8k16.row.col.f32.f16.f16.f32 "
        "{%0,%1,%2,%3},{%4,%5,%6,%7},{%8,%9},{%0,%1,%2,%3};"
        : "+f"(c[0]), "+f"(c[1]), "+f"(c[2]), "+f"(c[3])
        : "r"(a[0]), "r"(a[1]), "r"(a[2]), "r"(a[3]), "r"(b[0]), "r"(b[1]));
}
// A loader: lane ar=tid&31 (row), ac=(tid>>5)*16 (16 consecutive floats)
__device__ __forceinline__ void load_a_regs(float4 v[4], const float* __restrict__ x,
                                            int t, int ar, int ac) {
    int gr = t * 32 + ar;
    if (gr < NN) {
        const float4* p = (const float4*)(x + (size_t)gr * KIN + ac);
        v[0] = p[0]; v[1] = p[1]; v[2] = p[2]; v[3] = p[3];
    } else {
        v[0] = v[1] = v[2] = v[3] = make_float4(0.f, 0.f, 0.f, 0.f);
    }
}
__device__ __forceinline__ uint32_t pack2(float a, float b) {
    __half2 h = __floats2half2_rn(a, b);
    return *(uint32_t*)&h;
}
__device__ __forceinline__ void cvt_store_a(__half* sm, int buf, const float4 v[4],
                                            int ar, int ac) {
    uint32_t hi[4], lo[4];
#pragma unroll
    for (int j = 0; j < 2; j++) {
        float4 f0 = v[2 * j], f1 = v[2 * j + 1];
        hi[2 * j]     = pack2(f0.x, f0.y);
        hi[2 * j + 1] = pack2(f0.z, f0.w);
        hi[2 * j + 2] = pack2(f1.x, f1.y);
        hi[2 * j + 3] = pack2(f1.z, f1.w);
    }
    // recompute residuals
    __half* base = sm + ABUF(buf) + ar * SAS + ac;
#pragma unroll
    for (int j = 0; j < 4; j++) {
        float4 f = v[j];
        __half2* hp = (__half2*)&hi[j];
        float2 hf0 = __half22float2(*hp);
        lo[j] = pack2(f.x - hf0.x, f.y - hf0.y);
    }
    // NOTE: hi[] above packed pairs (x,y) and (z,w) in order; redo cleanly:
    uint32_t H[8], L[8];
#pragma unroll
    for (int j = 0; j < 4; j++) {
        float4 f = v[j];
        __half2 a = __floats2half2_rn(f.x, f.y);
        __half2 b = __floats2half2_rn(f.z, f.w);
        float2 fa = __half22float2(a), fb = __half22float2(b);
        __half2 ra = __floats2half2_rn(f.x - fa.x, f.y - fa.y);
        __half2 rb = __floats2half2_rn(f.z - fb.x, f.w - fb.y);
        H[2 * j] = *(uint32_t*)&a; H[2 * j + 1] = *(uint32_t*)&b;
        L[2 * j] = *(uint32_t*)&ra; L[2 * j + 1] = *(uint32_t*)&rb;
    }
    uint4* ah = (uint4*)base;
    uint4* al = (uint4*)(base + 32 * SAS);
    ah[0] = make_uint4(H[0], H[1], H[2], H[3]);
    ah[1] = make_uint4(H[4], H[5], H[6], H[7]);
    al[0] = make_uint4(L[0], L[1], L[2], L[3]);
    al[1] = make_uint4(L[4], L[5], L[6], L[7]);
}

__global__ void __launch_bounds__(256, 2) k_hmma1(const float* __restrict__ x,
                                                  const float* __restrict__ asrc,
                                                  const float* __restrict__ adst) {
    extern __shared__ __half sm[];
    uint32_t sbase = cvta_s(sm);
    int tid = threadIdx.x;
    int wid = tid >> 5, lane = tid & 31;
    int wm = wid >> 2, wn = wid & 3;           // 2x4 warp grid: 16 rows x 32 cols
    int col0 = blockIdx.y * 128;
    int cx = blockIdx.x;
    int h = blockIdx.y * 4 + wn;               // this warp's head

    // ---- load B half (once): 128 n x 128 k, hi/lo ----
    for (int i = tid; i < 2048; i += 256) {
        int n = i >> 4, k8 = (i & 15) * 8;
        uint4 hv = *(const uint4*)(g_Whi + (size_t)(col0 + n) * KIN + k8);
        uint4 lv = *(const uint4*)(g_Wlo + (size_t)(col0 + n) * KIN + k8);
        *(uint4*)(sm + OFF_BHI + n * SAS + k8) = hv;
        *(uint4*)(sm + OFF_BLO + n * SAS + k8) = lv;
    }

    // att vectors for fused asd: lane owns channels nt*8 + (lane&3)*2 (+1)
    float sa[8], da[8];
#pragma unroll
    for (int nt = 0; nt < 4; nt++)
#pragma unroll
        for (int j = 0; j < 2; j++) {
            int c = nt * 8 + (lane & 3) * 2 + j;
            sa[nt * 2 + j] = asrc[h * HD + c];
            da[nt * 2 + j] = adst[h * HD + c];
        }

    int ar = tid & 31;                 // A row 0..31
    int ac = (tid >> 5) * 16;          // 16 consecutive floats
    int blk = lane >> 3, rowin = lane & 7;
    int a_r = (blk & 1) * 8 + rowin, a_c = (blk >> 1) * 8;
    int b_n = (blk >> 1) * 8 + rowin, b_c = (blk & 1) * 8;
    const int T = (NN + 31) / 32;      // 1563

    int t = cx;
    {
        float4 v0[4];
        load_a_regs(v0, x, t, ar, ac);
        cvt_store_a(sm, 0, v0, ar, ac);
    }
    __syncthreads();

    int cur = 0;
    for (; t < T; t += NCTA) {
        int tn = t + NCTA;
        bool have_next = (tn < T);
        float4 vnext[4];
        if (have_next) load_a_regs(vnext, x, tn, ar, ac);   // LDGs in flight

        float acc[4][4] = {};
#pragma unroll
        for (int ks = 0; ks < 8; ks++) {
            int k0 = ks * 16;
            uint32_t ah4[4], al4[4], bh[2][4], bl[2][4];
            uint32_t aoff = (uint32_t)((ABUF(cur) + (wm * 16 + a_r) * SAS + k0 + a_c) * 2);
            ldmx4(ah4, sbase + aoff);
            ldmx4(al4, sbase + aoff + 32 * SAS * 2);
#pragma unroll
            for (int pr = 0; pr < 2; pr++) {
                int nB = wn * 32 + pr * 16 + b_n;
                uint32_t boff = (uint32_t)((OFF_BHI + nB * SAS + k0 + b_c) * 2);
                ldmx4(bh[pr], sbase + boff);
                ldmx4(bl[pr], sbase + boff + OFF_BLO * 2);
            }
#pragma unroll
            for (int nt = 0; nt < 4; nt++)
                mma16816(acc[nt], ah4, &bh[nt >> 1][(nt & 1) * 2]);
#pragma unroll
            for (int nt = 0; nt < 4; nt++)
                mma16816(acc[nt], al4, &bh[nt >> 1][(nt & 1) * 2]);
#pragma unroll
            for (int nt = 0; nt < 4; nt++)
                mma16816(acc[nt], ah4, &bl[nt >> 1][(nt & 1) * 2]);
        }

        // ---- fused asd: dot acc rows with att vectors (fp32, pre-rounding) --
        {
            float s0 = 0.f, d0 = 0.f, s8 = 0.f, d8 = 0.f;
#pragma unroll
            for (int nt = 0; nt < 4; nt++) {
                s0 += acc[nt][0] * sa[nt * 2] + acc[nt][1] * sa[nt * 2 + 1];
                d0 += acc[nt][0] * da[nt * 2] + acc[nt][1] * da[nt * 2 + 1];
                s8 += acc[nt][2] * sa[nt * 2] + acc[nt][3] * sa[nt * 2 + 1];
                d8 += acc[nt][2] * da[nt * 2] + acc[nt][3] * da[nt * 2 + 1];
            }
#pragma unroll
            for (int o = 1; o <= 2; o <<= 1) {
                s0 += __shfl_xor_sync(0xffffffffu, s0, o);
                d0 += __shfl_xor_sync(0xffffffffu, d0, o);
                s8 += __shfl_xor_sync(0xffffffffu, s8, o);
                d8 += __shfl_xor_sync(0xffffffffu, d8, o);
            }
            if ((lane & 3) == 0) {
                int r = t * 32 + wm * 16 + (lane >> 2);
                if (r < NN)     { g_as1[r * NH + h] = s0;       g_ad1[r * NH + h] = d0; }
                if (r + 8 < NN) { g_as1[(r + 8) * NH + h] = s8; g_ad1[(r + 8) * NH + h] = d8; }
            }
        }

        // ---- store fp16 h1 ----
        int r = t * 32 + wm * 16 + (lane >> 2);
#pragma unroll
        for (int nt = 0; nt < 4; nt++) {
            int gc = col0 + wn * 32 + nt * 8 + (lane & 3) * 2;
            if (r < NN)
                *(__half2*)(g_h1h + (size_t)r * C1 + gc) =
                    __floats2half2_rn(acc[nt][0], acc[nt][1]);
            if (r + 8 < NN)
                *(__half2*)(g_h1h + (size_t)(r + 8) * C1 + gc) =
                    __floats2half2_rn(acc[nt][2], acc[nt][3]);
        }

        if (have_next) cvt_store_a(sm, cur ^ 1, vnext, ar, ac);
        __syncthreads();
        cur ^= 1;
    }
}

// ---------------- layer-1 aggregation: warp/node, fp16 gather, unroll 4 ------
__device__ __forceinline__ void agg_edge(float aA, float aB, float adA, float adB,
                                         uint2 ua, uint2 ub,
                                         float4& acc0, float4& acc1,
                                         float& dA, float& dB) {
    float wA = __expf(lrelu(aA + adA));
    float wB = __expf(lrelu(aB + adB));
    dA += wA; dB += wB;
    __half2* h0 = (__half2*)&ua;
    __half2* h1 = (__half2*)&ub;
    float2 f0 = __half22float2(h0[0]), f1 = __half22float2(h0[1]);
    float2 f2 = __half22float2(h1[0]), f3 = __half22float2(h1[1]);
    acc0.x += wA * f0.x; acc0.y += wA * f0.y; acc0.z += wA * f1.x; acc0.w += wA * f1.y;
    acc1.x += wB * f2.x; acc1.y += wB * f2.y; acc1.z += wB * f3.x; acc1.w += wB * f3.y;
}

__global__ void k_agg1(const float* __restrict__ b1) {
    int warp = (blockIdx.x * blockDim.x + threadIdx.x) >> 5;
    if (warp >= NN) return;
    int lane = threadIdx.x & 31;
    int n = warp;
    int hA = lane >> 3, hB = hA + 4;
    int beg = g_rowptr[n], end = g_rowptr[n + 1];
    float adA = g_ad1[n * NH + hA], adB = g_ad1[n * NH + hB];

    float4 acc0 = make_float4(0.f, 0.f, 0.f, 0.f);
    float4 acc1 = make_float4(0.f, 0.f, 0.f, 0.f);
    float dA = 0.f, dB = 0.f;
    int i = beg;
    for (; i + 3 < end; i += 4) {
        int s0 = g_esrc[i], s1 = g_esrc[i + 1], s2 = g_esrc[i + 2], s3 = g_esrc[i + 3];
        float a0A = g_as1[s0 * NH + hA], a0B = g_as1[s0 * NH + hB];
        float a1A = g_as1[s1 * NH + hA], a1B = g_as1[s1 * NH + hB];
        float a2A = g_as1[s2 * NH + hA], a2B = g_as1[s2 * NH + hB];
        float a3A = g_as1[s3 * NH + hA], a3B = g_as1[s3 * NH + hB];
        const uint2* q0 = (const uint2*)(g_h1h + (size_t)s0 * C1);
        const uint2* q1 = (const uint2*)(g_h1h + (size_t)s1 * C1);
        const uint2* q2 = (const uint2*)(g_h1h + (size_t)s2 * C1);
        const uint2* q3 = (const uint2*)(g_h1h + (size_t)s3 * C1);
        uint2 u0a = q0[lane], u0b = q0[32 + lane];
        uint2 u1a = q1[lane], u1b = q1[32 + lane];
        uint2 u2a = q2[lane], u2b = q2[32 + lane];
        uint2 u3a = q3[lane], u3b = q3[32 + lane];
        agg_edge(a0A, a0B, adA, adB, u0a, u0b, acc0, acc1, dA, dB);
        agg_edge(a1A, a1B, adA, adB, u1a, u1b, acc0, acc1, dA, dB);
        agg_edge(a2A, a2B, adA, adB, u2a, u2b, acc0, acc1, dA, dB);
        agg_edge(a3A, a3B, adA, adB, u3a, u3b, acc0, acc1, dA, dB);
    }
    for (; i < end; i++) {
        int s = g_esrc[i];
        float aA = g_as1[s * NH + hA], aB = g_as1[s * NH + hB];
        const uint2* q = (const uint2*)(g_h1h + (size_t)s * C1);
        uint2 ua = q[lane], ub = q[32 + lane];
        agg_edge(aA, aB, adA, adB, ua, ub, acc0, acc1, dA, dB);
    }
    float iA = 1.f / dA, iB = 1.f / dB;
    const float4* bp = (const float4*)b1;
    float4 bb0 = bp[lane], bb1 = bp[32 + lane];
    float4 o0, o1;
    o0.x = elu1(acc0.x * iA + bb0.x); o0.y = elu1(acc0.y * iA + bb0.y);
    o0.z = elu1(acc0.z * iA + bb0.z); o0.w = elu1(acc0.w * iA + bb0.w);
    o1.x = elu1(acc1.x * iB + bb1.x); o1.y = elu1(acc1.y * iB + bb1.y);
    o1.z = elu1(acc1.z * iB + bb1.z); o1.w = elu1(acc1.w * iB + bb1.w);
    float4* op = (float4*)(g_h1out + (size_t)n * C1);
    op[lane] = o0;
    op[32 + lane] = o1;
}

// ---------------- GEMM2 (fused W2aug): h2 = h1out @ [W2|W2@as2|W2@ad2] -------
__global__ void k_gemm2(const float* __restrict__ W2,
                        const float* __restrict__ as2,
                        const float* __restrict__ ad2) {
    __shared__ float Ws[C1 * 12];
    for (int i = threadIdx.x; i < C1; i += blockDim.x) {
        float s = 0.f, d = 0.f;
#pragma unroll
        for (int c = 0; c < NC; c++) {
            float w = W2[i * NC + c];
            Ws[i * 12 + c] = w;
            s += w * as2[c];
            d += w * ad2[c];
        }
        Ws[i * 12 + 10] = s;
        Ws[i * 12 + 11] = d;
    }
    __syncthreads();
    int n = blockIdx.x * blockDim.x + threadIdx.x;
    if (n >= NN) return;
    float acc[12];
#pragma unroll
    for (int c = 0; c < 12; c++) acc[c] = 0.f;
    const float4* xp = (const float4*)(g_h1out + (size_t)n * C1);
    for (int q = 0; q < 64; q++) {
        float4 x = xp[q];
        const float* w = &Ws[(q * 4) * 12];
#pragma unroll
        for (int c = 0; c < 12; c++)
            acc[c] += x.x * w[c] + x.y * w[12 + c] + x.z * w[24 + c] + x.w * w[36 + c];
    }
#pragma unroll
    for (int c = 0; c < 12; c++) g_h2[n * 12 + c] = acc[c];
}

// ---------------- layer-2 agg + log-softmax ----------------
__global__ void k_agg2(const float* __restrict__ b2, float* __restrict__ out) {
    int warp = (blockIdx.x * blockDim.x + threadIdx.x) >> 5;
    if (warp >= NN) return;
    int lane = threadIdx.x & 31;
    int n = warp;
    float ad2v = g_h2[n * 12 + 11];
    int beg = g_rowptr[n], end = g_rowptr[n + 1];

    float4 A = make_float4(0.f, 0.f, 0.f, 0.f);
    float4 Bv = make_float4(0.f, 0.f, 0.f, 0.f);
    float c8 = 0.f, c9 = 0.f, den = 0.f;
    for (int i = beg + lane; i < end; i += 32) {
        int s = g_esrc[i];
        const float4* hp = (const float4*)(g_h2 + (size_t)s * 12);
        float4 r0 = hp[0], r1 = hp[1], r2 = hp[2];
        float w = __expf(lrelu(r2.z + ad2v));
        den += w;
        A.x += w * r0.x; A.y += w * r0.y; A.z += w * r0.z; A.w += w * r0.w;
        Bv.x += w * r1.x; Bv.y += w * r1.y; Bv.z += w * r1.z; Bv.w += w * r1.w;
        c8 += w * r2.x; c9 += w * r2.y;
    }
#pragma unroll
    for (int o = 16; o > 0; o >>= 1) {
        A.x += __shfl_xor_sync(0xffffffffu, A.x, o);
        A.y += __shfl_xor_sync(0xffffffffu, A.y, o);
        A.z += __shfl_xor_sync(0xffffffffu, A.z, o);
        A.w += __shfl_xor_sync(0xffffffffu, A.w, o);
        Bv.x += __shfl_xor_sync(0xffffffffu, Bv.x, o);
        Bv.y += __shfl_xor_sync(0xffffffffu, Bv.y, o);
        Bv.z += __shfl_xor_sync(0xffffffffu, Bv.z, o);
        Bv.w += __shfl_xor_sync(0xffffffffu, Bv.w, o);
        c8  += __shfl_xor_sync(0xffffffffu, c8, o);
        c9  += __shfl_xor_sync(0xffffffffu, c9, o);
        den += __shfl_xor_sync(0xffffffffu, den, o);
    }
    if (lane == 0) {
        float inv = 1.f / den;
        float v[NC];
        v[0] = A.x * inv + b2[0]; v[1] = A.y * inv + b2[1];
        v[2] = A.z * inv + b2[2]; v[3] = A.w * inv + b2[3];
        v[4] = Bv.x * inv + b2[4]; v[5] = Bv.y * inv + b2[5];
        v[6] = Bv.z * inv + b2[6]; v[7] = Bv.w * inv + b2[7];
        v[8] = c8 * inv + b2[8];  v[9] = c9 * inv + b2[9];
        float mx = v[0];
#pragma unroll
        for (int c = 1; c < NC; c++) mx = fmaxf(mx, v[c]);
        float sm = 0.f;
#pragma unroll
        for (int c = 0; c < NC; c++) sm += __expf(v[c] - mx);
        float l = mx + __logf(sm);
#pragma unroll
        for (int c = 0; c < NC; c++) out[(size_t)n * NC + c] = v[c] - l;
    }
}

// ---------------- launch ----------------
extern "C" void kernel_launch(void* const* d_in, const int* in_sizes, int n_in,
                              void* d_out, int out_size) {
    const float* x   = (const float*)d_in[0];
    const void*  ei  = d_in[1];
    const float* W1  = (const float*)d_in[2];
    const float* as1 = (const float*)d_in[3];
    const float* ad1 = (const float*)d_in[4];
    const float* b1  = (const float*)d_in[5];
    const float* W2  = (const float*)d_in[6];
    const float* as2 = (const float*)d_in[7];
    const float* ad2 = (const float*)d_in[8];
    const float* b2  = (const float*)d_in[9];
    float* out = (float*)d_out;

    int smem_bytes = SM_HALVES * (int)sizeof(__half);   // ~102 KB
    cudaFuncSetAttribute(k_hmma1, cudaFuncAttributeMaxDynamicSharedMemorySize, smem_bytes);

    k_initprep<<<(NN + 255) / 256, 256>>>(ei, W1);          // 1
    k_hist<<<(EP + 255) / 256, 256>>>(ei);                  // 2
    k_scan1<<<196, 256>>>();                                // 3
    dim3 gg(NCTA, 2);
    k_hmma1<<<gg, 256, smem_bytes>>>(x, as1, ad1);          // 4 <- ncu slot
    k_scan2<<<1, 256>>>();                                  // 5
    k_scan3<<<196, 256>>>();                                // 6
    k_scatter<<<(EP + 255) / 256, 256>>>(ei);               // 7
    k_agg1<<<(NN + 7) / 8, 256>>>(b1);                      // 8
    k_gemm2<<<(NN + 127) / 128, 128>>>(W2, as2, ad2);       // 9
    k_agg2<<<(NN + 7) / 8, 256>>>(b2, out);                 // 10
}

// round 10
// speedup vs baseline: 1.7337x; 1.0886x over previous
#include <cuda_runtime.h>
#include <cuda_fp16.h>
#include <math.h>
#include <stdint.h>

// ---------------- problem constants ----------------
#define NN   50000
#define EE   800000
#define EP   (EE + NN)
#define KIN  128
#define C1   256              // 8 heads * 32
#define NH   8
#define HD   32
#define NC   10
#define NEG  0.2f
#define NCTA 148

// ---------------- scratch globals ----------------
__device__ __align__(256) __half g_h1h[(size_t)NN * C1];       // x@W1 in fp16
__device__ __align__(256) float  g_h1out[(size_t)NN * C1];     // layer-1 out
__device__ __align__(256) float  g_as1[NN * NH];
__device__ __align__(256) float  g_ad1[NN * NH];
__device__ __align__(256) float  g_h2[NN * 12];
__device__ __align__(256) __half g_Wh[C1 * KIN];               // W1^T fp16 [n][k]
__device__ __align__(256) int    g_rowptr[NN + 1];
__device__ __align__(256) int    g_cursor[NN];
__device__ __align__(256) int    g_counts[NN];
__device__ __align__(256) int    g_esrc[EP];
__device__ __align__(256) int    g_bsums[256];
__device__ int g_is64;

// ---------------- small helpers ----------------
__device__ __forceinline__ int eidx(const void* p, long long i, int is64) {
    return is64 ? (int)((const long long*)p)[i] : ((const int*)p)[i];
}
__device__ __forceinline__ float lrelu(float x) { return x > 0.f ? x : NEG * x; }
__device__ __forceinline__ float elu1(float x)  { return x > 0.f ? x : (__expf(x) - 1.f); }

// ---------------- init: zero counts + dtype sniff + W1 fp16 transpose --------
__global__ void k_initprep(const void* ei, const float* __restrict__ W1) {
    int i = blockIdx.x * blockDim.x + threadIdx.x;
    if (i < NN) g_counts[i] = 0;
    if (i < KIN * C1) {
        int k = i >> 8, n = i & 255;
        g_Wh[n * KIN + k] = __float2half(W1[i]);   // W1[k][n] row-major
    }
    if (i == 0) {
        const long long* p = (const long long*)ei;
        int ok = 1;
        for (int q = 0; q < 64; q++) {
            long long v = p[q];
            if (v < 0 || v >= NN) ok = 0;
        }
        g_is64 = ok;
    }
}

// ---------------- CSR build ----------------
__global__ void k_hist(const void* ei) {
    int i = blockIdx.x * blockDim.x + threadIdx.x;
    if (i >= EP) return;
    int is64 = g_is64;
    int d = (i < EE) ? eidx(ei, (long long)EE + i, is64) : (i - EE);
    atomicAdd(&g_counts[d], 1);
}

__global__ void k_scan1() {
    __shared__ int s[256];
    int t = threadIdx.x;
    int i = blockIdx.x * 256 + t;
    s[t] = (i < NN) ? g_counts[i] : 0;
    __syncthreads();
    for (int o = 128; o > 0; o >>= 1) {
        if (t < o) s[t] += s[t + o];
        __syncthreads();
    }
    if (t == 0) g_bsums[blockIdx.x] = s[0];
}

__global__ void k_scan2() {
    __shared__ int s[256];
    int t = threadIdx.x;
    int v = (t < 196) ? g_bsums[t] : 0;
    s[t] = v;
    __syncthreads();
    for (int o = 1; o < 256; o <<= 1) {
        int x = (t >= o) ? s[t - o] : 0;
        __syncthreads();
        s[t] += x;
        __syncthreads();
    }
    g_bsums[t] = s[t] - v;
}

__global__ void k_scan3() {
    __shared__ int s[256];
    int t = threadIdx.x;
    int i = blockIdx.x * 256 + t;
    int v = (i < NN) ? g_counts[i] : 0;
    s[t] = v;
    __syncthreads();
    for (int o = 1; o < 256; o <<= 1) {
        int x = (t >= o) ? s[t - o] : 0;
        __syncthreads();
        s[t] += x;
        __syncthreads();
    }
    int excl = s[t] - v + g_bsums[blockIdx.x];
    if (i < NN) { g_rowptr[i] = excl; g_cursor[i] = excl; }
    if (i == 0) g_rowptr[NN] = EP;
}

__global__ void k_scatter(const void* ei) {
    int i = blockIdx.x * blockDim.x + threadIdx.x;
    if (i >= EP) return;
    int is64 = g_is64;
    int s, d;
    if (i < EE) {
        s = eidx(ei, i, is64);
        d = eidx(ei, (long long)EE + i, is64);
    } else {
        s = d = i - EE;
    }
    int pos = atomicAdd(&g_cursor[d], 1);
    g_esrc[pos] = s;
}

// ---------------- GEMM1 + attn-logits: persistent fp16 mma, full N=256 -------
// Grid (148,1). CTA holds all of W^T fp16 in SMEM (once); walks 32-row M-tiles
// with double-buffered A. Warp wn owns cols [wn*64, wn*64+64) = heads 2wn,2wn+1;
// a_s/a_d computed from fp32 accumulators.
#define SAS 136
#define OFF_B 0
#define OFF_A (256 * SAS)
#define ABUF(b) (OFF_A + (b) * (32 * SAS))
#define SM_HALVES (OFF_A + 2 * 32 * SAS)        // 320*SAS halves ≈ 85 KB

__device__ __forceinline__ uint32_t cvta_s(const void* p) {
    uint32_t a;
    asm("{ .reg .u64 t; cvta.to.shared.u64 t, %1; cvt.u32.u64 %0, t; }" : "=r"(a) : "l"(p));
    return a;
}
__device__ __forceinline__ void ldmx4(uint32_t r[4], uint32_t addr) {
    asm volatile("ldmatrix.sync.aligned.m8n8.x4.shared.b16 {%0,%1,%2,%3}, [%4];"
                 : "=r"(r[0]), "=r"(r[1]), "=r"(r[2]), "=r"(r[3]) : "r"(addr));
}
__device__ __forceinline__ void mma16816(float c[4], const uint32_t a[4], const uint32_t b[2]) {
    asm volatile(
        "mma.sync.aligned.m16n8k16.row.col.f32.f16.f16.f32 "
        "{%0,%1,%2,%3},{%4,%5,%6,%7},{%8,%9},{%0,%1,%2,%3};"
        : "+f"(c[0]), "+f"(c[1]), "+f"(c[2]), "+f"(c[3])
        : "r"(a[0]), "r"(a[1]), "r"(a[2]), "r"(a[3]), "r"(b[0]), "r"(b[1]));
}
__device__ __forceinline__ void load_a_regs(float4 v[4], const float* __restrict__ x,
                                            int t, int ar, int ac) {
    int gr = t * 32 + ar;
    if (gr < NN) {
        const float4* p = (const float4*)(x + (size_t)gr * KIN + ac);
        v[0] = p[0]; v[1] = p[1]; v[2] = p[2]; v[3] = p[3];
    } else {
        v[0] = v[1] = v[2] = v[3] = make_float4(0.f, 0.f, 0.f, 0.f);
    }
}
__device__ __forceinline__ void cvt_store_a(__half* sm, int buf, const float4 v[4],
                                            int ar, int ac) {
    uint32_t H[8];
#pragma unroll
    for (int j = 0; j < 4; j++) {
        __half2 a = __floats2half2_rn(v[j].x, v[j].y);
        __half2 b = __floats2half2_rn(v[j].z, v[j].w);
        H[2 * j] = *(uint32_t*)&a; H[2 * j + 1] = *(uint32_t*)&b;
    }
    uint4* ah = (uint4*)(sm + ABUF(buf) + ar * SAS + ac);
    ah[0] = make_uint4(H[0], H[1], H[2], H[3]);
    ah[1] = make_uint4(H[4], H[5], H[6], H[7]);
}

__global__ void __launch_bounds__(256, 2) k_hmma1(const float* __restrict__ x,
                                                  const float* __restrict__ asrc,
                                                  const float* __restrict__ adst) {
    extern __shared__ __half sm[];
    uint32_t sbase = cvta_s(sm);
    int tid = threadIdx.x;
    int wid = tid >> 5, lane = tid & 31;
    int wm = wid >> 2, wn = wid & 3;           // 2x4 warps: 16 rows x 64 cols each
    int cx = blockIdx.x;
    int hA = 2 * wn, hB = 2 * wn + 1;          // heads owned by this warp

    // ---- load full B: 256 n x 128 k fp16 (once) ----
    for (int i = tid; i < 4096; i += 256) {
        int n = i >> 4, k8 = (i & 15) * 8;
        *(uint4*)(sm + OFF_B + n * SAS + k8) =
            *(const uint4*)(g_Wh + (size_t)n * KIN + k8);
    }

    // attention vectors: lane owns channels j8*8 + (lane&3)*2 (+1) of each head
    float saA[8], daA[8], saB[8], daB[8];
#pragma unroll
    for (int j8 = 0; j8 < 4; j8++)
#pragma unroll
        for (int j = 0; j < 2; j++) {
            int c = j8 * 8 + (lane & 3) * 2 + j;
            saA[j8 * 2 + j] = asrc[hA * HD + c];
            daA[j8 * 2 + j] = adst[hA * HD + c];
            saB[j8 * 2 + j] = asrc[hB * HD + c];
            daB[j8 * 2 + j] = adst[hB * HD + c];
        }

    int ar = tid & 31;                 // A row 0..31
    int ac = (tid >> 5) * 16;          // 16 consecutive floats
    int blk = lane >> 3, rowin = lane & 7;
    int a_r = (blk & 1) * 8 + rowin, a_c = (blk >> 1) * 8;
    int b_n = (blk >> 1) * 8 + rowin, b_c = (blk & 1) * 8;
    const int T = (NN + 31) / 32;      // 1563

    int t = cx;
    {
        float4 v0[4];
        load_a_regs(v0, x, t, ar, ac);
        cvt_store_a(sm, 0, v0, ar, ac);
    }
    __syncthreads();

    int cur = 0;
    for (; t < T; t += NCTA) {
        int tn = t + NCTA;
        bool have_next = (tn < T);
        float4 vnext[4];
        if (have_next) load_a_regs(vnext, x, tn, ar, ac);   // LDGs in flight

        float acc[8][4] = {};
#pragma unroll
        for (int ks = 0; ks < 8; ks++) {
            int k0 = ks * 16;
            uint32_t a4[4], b4[4][4];
            uint32_t aoff = (uint32_t)((ABUF(cur) + (wm * 16 + a_r) * SAS + k0 + a_c) * 2);
            ldmx4(a4, sbase + aoff);
#pragma unroll
            for (int pr = 0; pr < 4; pr++) {
                int nB = wn * 64 + pr * 16 + b_n;
                uint32_t boff = (uint32_t)((OFF_B + nB * SAS + k0 + b_c) * 2);
                ldmx4(b4[pr], sbase + boff);
            }
#pragma unroll
            for (int nt = 0; nt < 8; nt++)
                mma16816(acc[nt], a4, &b4[nt >> 1][(nt & 1) * 2]);
        }

        // ---- fused asd from fp32 accumulators ----
        {
            float sA0 = 0.f, dA0 = 0.f, sA8 = 0.f, dA8 = 0.f;
            float sB0 = 0.f, dB0 = 0.f, sB8 = 0.f, dB8 = 0.f;
#pragma unroll
            for (int j8 = 0; j8 < 4; j8++) {
                sA0 += acc[j8][0] * saA[j8 * 2] + acc[j8][1] * saA[j8 * 2 + 1];
                dA0 += acc[j8][0] * daA[j8 * 2] + acc[j8][1] * daA[j8 * 2 + 1];
                sA8 += acc[j8][2] * saA[j8 * 2] + acc[j8][3] * saA[j8 * 2 + 1];
                dA8 += acc[j8][2] * daA[j8 * 2] + acc[j8][3] * daA[j8 * 2 + 1];
                sB0 += acc[4 + j8][0] * saB[j8 * 2] + acc[4 + j8][1] * saB[j8 * 2 + 1];
                dB0 += acc[4 + j8][0] * daB[j8 * 2] + acc[4 + j8][1] * daB[j8 * 2 + 1];
                sB8 += acc[4 + j8][2] * saB[j8 * 2] + acc[4 + j8][3] * saB[j8 * 2 + 1];
                dB8 += acc[4 + j8][2] * daB[j8 * 2] + acc[4 + j8][3] * daB[j8 * 2 + 1];
            }
#pragma unroll
            for (int o = 1; o <= 2; o <<= 1) {
                sA0 += __shfl_xor_sync(0xffffffffu, sA0, o);
                dA0 += __shfl_xor_sync(0xffffffffu, dA0, o);
                sA8 += __shfl_xor_sync(0xffffffffu, sA8, o);
                dA8 += __shfl_xor_sync(0xffffffffu, dA8, o);
                sB0 += __shfl_xor_sync(0xffffffffu, sB0, o);
                dB0 += __shfl_xor_sync(0xffffffffu, dB0, o);
                sB8 += __shfl_xor_sync(0xffffffffu, sB8, o);
                dB8 += __shfl_xor_sync(0xffffffffu, dB8, o);
            }
            if ((lane & 3) == 0) {
                int r = t * 32 + wm * 16 + (lane >> 2);
                if (r < NN) {
                    g_as1[r * NH + hA] = sA0; g_ad1[r * NH + hA] = dA0;
                    g_as1[r * NH + hB] = sB0; g_ad1[r * NH + hB] = dB0;
                }
                if (r + 8 < NN) {
                    g_as1[(r + 8) * NH + hA] = sA8; g_ad1[(r + 8) * NH + hA] = dA8;
                    g_as1[(r + 8) * NH + hB] = sB8; g_ad1[(r + 8) * NH + hB] = dB8;
                }
            }
        }

        // ---- store fp16 h1 ----
        int r = t * 32 + wm * 16 + (lane >> 2);
#pragma unroll
        for (int nt = 0; nt < 8; nt++) {
            int gc = wn * 64 + nt * 8 + (lane & 3) * 2;
            if (r < NN)
                *(__half2*)(g_h1h + (size_t)r * C1 + gc) =
                    __floats2half2_rn(acc[nt][0], acc[nt][1]);
            if (r + 8 < NN)
                *(__half2*)(g_h1h + (size_t)(r + 8) * C1 + gc) =
                    __floats2half2_rn(acc[nt][2], acc[nt][3]);
        }

        if (have_next) cvt_store_a(sm, cur ^ 1, vnext, ar, ac);
        __syncthreads();
        cur ^= 1;
    }
}

// ---------------- layer-1 aggregation: warp/node, fp16 gather, unroll 4 ------
__device__ __forceinline__ void agg_edge(float aA, float aB, float adA, float adB,
                                         uint2 ua, uint2 ub,
                                         float4& acc0, float4& acc1,
                                         float& dA, float& dB) {
    float wA = __expf(lrelu(aA + adA));
    float wB = __expf(lrelu(aB + adB));
    dA += wA; dB += wB;
    __half2* h0 = (__half2*)&ua;
    __half2* h1 = (__half2*)&ub;
    float2 f0 = __half22float2(h0[0]), f1 = __half22float2(h0[1]);
    float2 f2 = __half22float2(h1[0]), f3 = __half22float2(h1[1]);
    acc0.x += wA * f0.x; acc0.y += wA * f0.y; acc0.z += wA * f1.x; acc0.w += wA * f1.y;
    acc1.x += wB * f2.x; acc1.y += wB * f2.y; acc1.z += wB * f3.x; acc1.w += wB * f3.y;
}

__global__ void k_agg1(const float* __restrict__ b1) {
    int warp = (blockIdx.x * blockDim.x + threadIdx.x) >> 5;
    if (warp >= NN) return;
    int lane = threadIdx.x & 31;
    int n = warp;
    int hA = lane >> 3, hB = hA + 4;
    int beg = g_rowptr[n], end = g_rowptr[n + 1];
    float adA = g_ad1[n * NH + hA], adB = g_ad1[n * NH + hB];

    float4 acc0 = make_float4(0.f, 0.f, 0.f, 0.f);
    float4 acc1 = make_float4(0.f, 0.f, 0.f, 0.f);
    float dA = 0.f, dB = 0.f;
    int i = beg;
    for (; i + 3 < end; i += 4) {
        int s0 = g_esrc[i], s1 = g_esrc[i + 1], s2 = g_esrc[i + 2], s3 = g_esrc[i + 3];
        float a0A = g_as1[s0 * NH + hA], a0B = g_as1[s0 * NH + hB];
        float a1A = g_as1[s1 * NH + hA], a1B = g_as1[s1 * NH + hB];
        float a2A = g_as1[s2 * NH + hA], a2B = g_as1[s2 * NH + hB];
        float a3A = g_as1[s3 * NH + hA], a3B = g_as1[s3 * NH + hB];
        const uint2* q0 = (const uint2*)(g_h1h + (size_t)s0 * C1);
        const uint2* q1 = (const uint2*)(g_h1h + (size_t)s1 * C1);
        const uint2* q2 = (const uint2*)(g_h1h + (size_t)s2 * C1);
        const uint2* q3 = (const uint2*)(g_h1h + (size_t)s3 * C1);
        uint2 u0a = q0[lane], u0b = q0[32 + lane];
        uint2 u1a = q1[lane], u1b = q1[32 + lane];
        uint2 u2a = q2[lane], u2b = q2[32 + lane];
        uint2 u3a = q3[lane], u3b = q3[32 + lane];
        agg_edge(a0A, a0B, adA, adB, u0a, u0b, acc0, acc1, dA, dB);
        agg_edge(a1A, a1B, adA, adB, u1a, u1b, acc0, acc1, dA, dB);
        agg_edge(a2A, a2B, adA, adB, u2a, u2b, acc0, acc1, dA, dB);
        agg_edge(a3A, a3B, adA, adB, u3a, u3b, acc0, acc1, dA, dB);
    }
    for (; i < end; i++) {
        int s = g_esrc[i];
        float aA = g_as1[s * NH + hA], aB = g_as1[s * NH + hB];
        const uint2* q = (const uint2*)(g_h1h + (size_t)s * C1);
        uint2 ua = q[lane], ub = q[32 + lane];
        agg_edge(aA, aB, adA, adB, ua, ub, acc0, acc1, dA, dB);
    }
    float iA = 1.f / dA, iB = 1.f / dB;
    const float4* bp = (const float4*)b1;
    float4 bb0 = bp[lane], bb1 = bp[32 + lane];
    float4 o0, o1;
    o0.x = elu1(acc0.x * iA + bb0.x); o0.y = elu1(acc0.y * iA + bb0.y);
    o0.z = elu1(acc0.z * iA + bb0.z); o0.w = elu1(acc0.w * iA + bb0.w);
    o1.x = elu1(acc1.x * iB + bb1.x); o1.y = elu1(acc1.y * iB + bb1.y);
    o1.z = elu1(acc1.z * iB + bb1.z); o1.w = elu1(acc1.w * iB + bb1.w);
    float4* op = (float4*)(g_h1out + (size_t)n * C1);
    op[lane] = o0;
    op[32 + lane] = o1;
}

// ---------------- GEMM2 (fused W2aug): h2 = h1out @ [W2|W2@as2|W2@ad2] -------
__global__ void k_gemm2(const float* __restrict__ W2,
                        const float* __restrict__ as2,
                        const float* __restrict__ ad2) {
    __shared__ float Ws[C1 * 12];
    for (int i = threadIdx.x; i < C1; i += blockDim.x) {
        float s = 0.f, d = 0.f;
#pragma unroll
        for (int c = 0; c < NC; c++) {
            float w = W2[i * NC + c];
            Ws[i * 12 + c] = w;
            s += w * as2[c];
            d += w * ad2[c];
        }
        Ws[i * 12 + 10] = s;
        Ws[i * 12 + 11] = d;
    }
    __syncthreads();
    int n = blockIdx.x * blockDim.x + threadIdx.x;
    if (n >= NN) return;
    float acc[12];
#pragma unroll
    for (int c = 0; c < 12; c++) acc[c] = 0.f;
    const float4* xp = (const float4*)(g_h1out + (size_t)n * C1);
    for (int q = 0; q < 64; q++) {
        float4 x = xp[q];
        const float* w = &Ws[(q * 4) * 12];
#pragma unroll
        for (int c = 0; c < 12; c++)
            acc[c] += x.x * w[c] + x.y * w[12 + c] + x.z * w[24 + c] + x.w * w[36 + c];
    }
#pragma unroll
    for (int c = 0; c < 12; c++) g_h2[n * 12 + c] = acc[c];
}

// ---------------- layer-2 agg + log-softmax ----------------
__global__ void k_agg2(const float* __restrict__ b2, float* __restrict__ out) {
    int warp = (blockIdx.x * blockDim.x + threadIdx.x) >> 5;
    if (warp >= NN) return;
    int lane = threadIdx.x & 31;
    int n = warp;
    float ad2v = g_h2[n * 12 + 11];
    int beg = g_rowptr[n], end = g_rowptr[n + 1];

    float4 A = make_float4(0.f, 0.f, 0.f, 0.f);
    float4 Bv = make_float4(0.f, 0.f, 0.f, 0.f);
    float c8 = 0.f, c9 = 0.f, den = 0.f;
    for (int i = beg + lane; i < end; i += 32) {
        int s = g_esrc[i];
        const float4* hp = (const float4*)(g_h2 + (size_t)s * 12);
        float4 r0 = hp[0], r1 = hp[1], r2 = hp[2];
        float w = __expf(lrelu(r2.z + ad2v));
        den += w;
        A.x += w * r0.x; A.y += w * r0.y; A.z += w * r0.z; A.w += w * r0.w;
        Bv.x += w * r1.x; Bv.y += w * r1.y; Bv.z += w * r1.z; Bv.w += w * r1.w;
        c8 += w * r2.x; c9 += w * r2.y;
    }
#pragma unroll
    for (int o = 16; o > 0; o >>= 1) {
        A.x += __shfl_xor_sync(0xffffffffu, A.x, o);
        A.y += __shfl_xor_sync(0xffffffffu, A.y, o);
        A.z += __shfl_xor_sync(0xffffffffu, A.z, o);
        A.w += __shfl_xor_sync(0xffffffffu, A.w, o);
        Bv.x += __shfl_xor_sync(0xffffffffu, Bv.x, o);
        Bv.y += __shfl_xor_sync(0xffffffffu, Bv.y, o);
        Bv.z += __shfl_xor_sync(0xffffffffu, Bv.z, o);
        Bv.w += __shfl_xor_sync(0xffffffffu, Bv.w, o);
        c8  += __shfl_xor_sync(0xffffffffu, c8, o);
        c9  += __shfl_xor_sync(0xffffffffu, c9, o);
        den += __shfl_xor_sync(0xffffffffu, den, o);
    }
    if (lane == 0) {
        float inv = 1.f / den;
        float v[NC];
        v[0] = A.x * inv + b2[0]; v[1] = A.y * inv + b2[1];
        v[2] = A.z * inv + b2[2]; v[3] = A.w * inv + b2[3];
        v[4] = Bv.x * inv + b2[4]; v[5] = Bv.y * inv + b2[5];
        v[6] = Bv.z * inv + b2[6]; v[7] = Bv.w * inv + b2[7];
        v[8] = c8 * inv + b2[8];  v[9] = c9 * inv + b2[9];
        float mx = v[0];
#pragma unroll
        for (int c = 1; c < NC; c++) mx = fmaxf(mx, v[c]);
        float sm = 0.f;
#pragma unroll
        for (int c = 0; c < NC; c++) sm += __expf(v[c] - mx);
        float l = mx + __logf(sm);
#pragma unroll
        for (int c = 0; c < NC; c++) out[(size_t)n * NC + c] = v[c] - l;
    }
}

// ---------------- launch ----------------
extern "C" void kernel_launch(void* const* d_in, const int* in_sizes, int n_in,
                              void* d_out, int out_size) {
    const float* x   = (const float*)d_in[0];
    const void*  ei  = d_in[1];
    const float* W1  = (const float*)d_in[2];
    const float* as1 = (const float*)d_in[3];
    const float* ad1 = (const float*)d_in[4];
    const float* b1  = (const float*)d_in[5];
    const float* W2  = (const float*)d_in[6];
    const float* as2 = (const float*)d_in[7];
    const float* ad2 = (const float*)d_in[8];
    const float* b2  = (const float*)d_in[9];
    float* out = (float*)d_out;

    int smem_bytes = SM_HALVES * (int)sizeof(__half);   // ~85 KB
    cudaFuncSetAttribute(k_hmma1, cudaFuncAttributeMaxDynamicSharedMemorySize, smem_bytes);

    k_initprep<<<(NN + 255) / 256, 256>>>(ei, W1);          // 1
    k_hist<<<(EP + 255) / 256, 256>>>(ei);                  // 2
    k_scan1<<<196, 256>>>();                                // 3
    k_hmma1<<<NCTA, 256, smem_bytes>>>(x, as1, ad1);        // 4 <- ncu slot
    k_scan2<<<1, 256>>>();                                  // 5
    k_scan3<<<196, 256>>>();                                // 6
    k_scatter<<<(EP + 255) / 256, 256>>>(ei);               // 7
    k_agg1<<<(NN + 7) / 8, 256>>>(b1);                      // 8
    k_gemm2<<<(NN + 127) / 128, 128>>>(W2, as2, ad2);       // 9
    k_agg2<<<(NN + 7) / 8, 256>>>(b2, out);                 // 10
}